// round 5
// baseline (speedup 1.0000x reference)
#include <cuda_runtime.h>
#include <cfloat>
#include <cstddef>

#define NPTS 2048
#define BATCH 4
#define KNN 20
#define NSPLIT 4
#define JSPAN (NPTS / NSPLIT)   /* 512 */

// ---------------- scratch (device globals; no allocation allowed) ----------
__device__ float g_x0[BATCH * 3 * NPTS];
// concat feature buffer: (B, 512, N). x1 @ ch 0, x2 @ 64, x3 @ 128, x4 @ 256
__device__ float g_xcat[(size_t)BATCH * 512 * NPTS];
__device__ float g_xx[BATCH * NPTS];
__device__ int   g_knn[BATCH * NPTS * KNN];
__device__ float g_pLv[(size_t)BATCH * NPTS * NSPLIT * KNN];  // partial lists
__device__ int   g_pLi[(size_t)BATCH * NPTS * NSPLIT * KNN];
__device__ float g_Y[BATCH * NPTS * 256];                // n-major, stride 256
__device__ float g_Z[BATCH * NPTS * 256];
__device__ float g_h5[(size_t)BATCH * NPTS * 1024];      // 32 MB
__device__ float g_f[BATCH * 2048];
__device__ float g_fc1[BATCH * 512];

__device__ __forceinline__ float lrelu(float v) { return v > 0.f ? v : 0.2f * v; }
#define BN_RSQ 0.99999500003749968750f  /* rsqrt(1+1e-5) */
#define CAT_BSTR (512 * NPTS)

// ---------------- transpose points (B,N,3) -> (B,3,N) ----------------------
__global__ void k_transpose(const float* __restrict__ pts) {
    int i = blockIdx.x * blockDim.x + threadIdx.x;
    if (i < BATCH * NPTS) {
        int b = i / NPTS, n = i % NPTS;
        #pragma unroll
        for (int c = 0; c < 3; c++)
            g_x0[(b * 3 + c) * NPTS + n] = pts[(b * NPTS + n) * 3 + c];
    }
}

// ---------------- row norms ------------------------------------------------
__global__ void k_xx(const float* __restrict__ feat, int C, int bstr) {
    int i = blockIdx.x * blockDim.x + threadIdx.x;
    if (i < BATCH * NPTS) {
        int b = i / NPTS, n = i % NPTS;
        const float* f = feat + (size_t)b * bstr + n;
        float s = 0.f;
        for (int c = 0; c < C; c++) { float v = f[(size_t)c * NPTS]; s = fmaf(v, v, s); }
        g_xx[i] = s;
    }
}

// ---------------- FUSED distance GEMM + partial top-K ----------------------
// grid (N/64, NSPLIT, B), 256 threads, 28KB static smem.
// Block computes 64 i-rows x 512 j-cols (its split), maintains per-row
// top-20 over its j-range; per-warp row staging (8x256 scratch). Exact
// ascending-j candidate order within the split; >=-position insert =>
// equal values keep earlier index.
__global__ void k_dist_topk(const float* __restrict__ feat, int C, int bstr) {
    __shared__ float As[8 * 64];
    __shared__ float Bs[8 * 256];
    __shared__ float Srow[8 * 256];     // per-warp 256-float row scratch
    __shared__ float Lv[64 * KNN];
    __shared__ int   Li[64 * KNN];

    int b = blockIdx.z;
    int split = blockIdx.y;
    int i0 = blockIdx.x * 64;
    const float* fb = feat + (size_t)b * bstr;
    int tid = threadIdx.x;
    int lane = tid & 31, warp = tid >> 5;
    const unsigned FULL = 0xffffffffu;

    for (int e = tid; e < 64 * KNN; e += 256) {
        Lv[e] = -FLT_MAX;
        Li[e] = 0x7FFFFFFF;
    }
    __syncthreads();

    for (int jt = 0; jt < JSPAN; jt += 256) {
        int j0 = split * JSPAN + jt;
        // ---- GEMM 64x256 ----
        float acc[8][8] = {};
        for (int c0 = 0; c0 < C; c0 += 8) {
            if (tid < 128) {                       // As: 8x64
                int kk = tid >> 4, ii = (tid & 15) * 4;
                int c = c0 + kk;
                float4 v = {0.f, 0.f, 0.f, 0.f};
                if (c < C) v = *(const float4*)&fb[(size_t)c * NPTS + i0 + ii];
                *(float4*)&As[kk * 64 + ii] = v;
            }
            {                                       // Bs: 8x256
                int kk = warp;
                int c = c0 + kk;
                float4 v0 = {0.f, 0.f, 0.f, 0.f}, v1 = v0;
                if (c < C) {
                    v0 = *(const float4*)&fb[(size_t)c * NPTS + j0 + lane * 4];
                    v1 = *(const float4*)&fb[(size_t)c * NPTS + j0 + 128 + lane * 4];
                }
                *(float4*)&Bs[kk * 256 + lane * 4] = v0;
                *(float4*)&Bs[kk * 256 + 128 + lane * 4] = v1;
            }
            __syncthreads();
            #pragma unroll
            for (int kk = 0; kk < 8; kk++) {
                float a[8], bb[8];
                *(float4*)&a[0] = *(const float4*)&As[kk * 64 + warp * 8];
                *(float4*)&a[4] = *(const float4*)&As[kk * 64 + warp * 8 + 4];
                *(float4*)&bb[0] = *(const float4*)&Bs[kk * 256 + lane * 8];
                *(float4*)&bb[4] = *(const float4*)&Bs[kk * 256 + lane * 8 + 4];
                #pragma unroll
                for (int r = 0; r < 8; r++)
                    #pragma unroll
                    for (int s = 0; s < 8; s++)
                        acc[r][s] = fmaf(a[r], bb[s], acc[r][s]);
            }
            __syncthreads();
        }
        // ---- per-warp: epilogue + top-k update, one row at a time ----
        float xjv[8];
        #pragma unroll
        for (int s = 0; s < 8; s++) xjv[s] = g_xx[b * NPTS + j0 + lane * 8 + s];
        #pragma unroll 1
        for (int rr = 0; rr < 8; rr++) {
            int r = warp * 8 + rr;
            float xi = g_xx[b * NPTS + i0 + r];
            float o[8];
            #pragma unroll
            for (int s = 0; s < 8; s++) o[s] = 2.f * acc[rr][s] - xi - xjv[s];
            *(float4*)&Srow[warp * 256 + lane * 8] = *(float4*)&o[0];
            *(float4*)&Srow[warp * 256 + lane * 8 + 4] = *(float4*)&o[4];
            __syncwarp();
            float kth = Lv[r * KNN + KNN - 1];
            #pragma unroll 1
            for (int m = 0; m < 8; m++) {
                float v = Srow[warp * 256 + lane + 32 * m];
                unsigned mask = __ballot_sync(FULL, v > kth);
                while (mask) {
                    int src = __ffs(mask) - 1;
                    mask &= mask - 1;
                    float vs = __shfl_sync(FULL, v, src);
                    if (vs > kth) {                 // recheck vs updated kth
                        int js = j0 + src + 32 * m;
                        float Lq = (lane < KNN) ? Lv[r * KNN + lane] : -FLT_MAX;
                        int   Iq = (lane < KNN) ? Li[r * KNN + lane] : 0x7FFFFFFF;
                        unsigned bef = __ballot_sync(FULL, (lane < KNN) && (Lq >= vs));
                        int p = __popc(bef);
                        float sv = __shfl_up_sync(FULL, Lq, 1);
                        int   si = __shfl_up_sync(FULL, Iq, 1);
                        float nLq = (lane < p) ? Lq : (lane == p ? vs : sv);
                        int   nIq = (lane < p) ? Iq : (lane == p ? js : si);
                        if (lane < KNN) {
                            Lv[r * KNN + lane] = nLq;
                            Li[r * KNN + lane] = nIq;
                        }
                        kth = __shfl_sync(FULL, nLq, KNN - 1);
                    }
                }
            }
            __syncwarp();
        }
        __syncthreads();
    }
    // ---- write partial lists (sorted desc, ties index-asc) ----
    #pragma unroll 1
    for (int rr = 0; rr < 8; rr++) {
        int r = warp * 8 + rr;
        if (lane < KNN) {
            size_t base = (((size_t)b * NPTS + i0 + r) * NSPLIT + split) * KNN + lane;
            g_pLv[base] = Lv[r * KNN + lane];
            g_pLi[base] = Li[r * KNN + lane];
        }
    }
}

// ---------------- merge NSPLIT sorted partial lists -> g_knn ---------------
// 1 thread/row; exact (value desc, index asc) 4-way merge.
__global__ void k_merge() {
    int row = blockIdx.x * 256 + threadIdx.x;        // b*NPTS + n
    if (row >= BATCH * NPTS) return;
    const float* pv = g_pLv + (size_t)row * NSPLIT * KNN;
    const int*   pi = g_pLi + (size_t)row * NSPLIT * KNN;
    int p[NSPLIT] = {0, 0, 0, 0};
    #pragma unroll 1
    for (int k = 0; k < KNN; k++) {
        float bv = -FLT_MAX;
        int bi = 0x7FFFFFFF, sel = 0;
        #pragma unroll
        for (int s = 0; s < NSPLIT; s++) {
            if (p[s] < KNN) {
                float v = pv[s * KNN + p[s]];
                int   i = pi[s * KNN + p[s]];
                if (v > bv || (v == bv && i < bi)) { bv = v; bi = i; sel = s; }
            }
        }
        g_knn[(size_t)row * KNN + k] = bi;
        p[sel]++;
    }
}

// ---------------- Y = W2 X, Z = (W1-W2) X ; stored n-major stride 256 ------
// grid (N/64, Cout/64, B), 256 threads
__global__ void k_yz(const float* __restrict__ feat, const float* __restrict__ W,
                     int C, int Cout, int bstr) {
    __shared__ float As[16][64];
    __shared__ float B1[16][64];
    __shared__ float B2[16][64];
    int b = blockIdx.z;
    int n0 = blockIdx.x * 64, o0 = blockIdx.y * 64;
    const float* fb = feat + (size_t)b * bstr;
    int tx = threadIdx.x & 15, ty = threadIdx.x >> 4;
    float aU[4][4] = {}, aY[4][4] = {};
    for (int c0 = 0; c0 < C; c0 += 16) {
        for (int e = threadIdx.x; e < 1024; e += 256) {
            int kk = e >> 6, nn = e & 63;
            int c = c0 + kk;
            As[kk][nn] = (c < C) ? fb[(size_t)c * NPTS + n0 + nn] : 0.f;
        }
        for (int e = threadIdx.x; e < 1024; e += 256) {
            int kk = e & 15, oo = e >> 4;
            int c = c0 + kk;
            float w1 = 0.f, w2 = 0.f;
            if (c < C) {
                const float* wr = W + (size_t)(o0 + oo) * (2 * C);
                w1 = wr[c]; w2 = wr[C + c];
            }
            B1[kk][oo] = w1; B2[kk][oo] = w2;
        }
        __syncthreads();
        #pragma unroll
        for (int kk = 0; kk < 16; kk++) {
            float4 a4 = *(const float4*)&As[kk][ty * 4];
            float4 b14 = *(const float4*)&B1[kk][tx * 4];
            float4 b24 = *(const float4*)&B2[kk][tx * 4];
            float av[4] = {a4.x, a4.y, a4.z, a4.w};
            float b1v[4] = {b14.x, b14.y, b14.z, b14.w};
            float b2v[4] = {b24.x, b24.y, b24.z, b24.w};
            #pragma unroll
            for (int r = 0; r < 4; r++)
                #pragma unroll
                for (int s = 0; s < 4; s++) {
                    aU[r][s] = fmaf(av[r], b1v[s], aU[r][s]);
                    aY[r][s] = fmaf(av[r], b2v[s], aY[r][s]);
                }
        }
        __syncthreads();
    }
    #pragma unroll
    for (int r = 0; r < 4; r++) {
        int n = n0 + ty * 4 + r;
        size_t base = ((size_t)b * NPTS + n) * 256 + o0 + tx * 4;
        float4 y, z;
        y.x = aY[r][0]; y.y = aY[r][1]; y.z = aY[r][2]; y.w = aY[r][3];
        z.x = aU[r][0] - y.x; z.y = aU[r][1] - y.y;
        z.z = aU[r][2] - y.z; z.w = aU[r][3] - y.w;
        *(float4*)&g_Y[base] = y;
        *(float4*)&g_Z[base] = z;
    }
}

// ---------------- gather-max + BN + lrelu -> out slice of g_xcat -----------
// grid (N/32, B), blockDim = Cout
__global__ void k_gather(float* __restrict__ out, const float* __restrict__ gam,
                         const float* __restrict__ bet, int Cout, int bstr) {
    __shared__ int   sidx[32 * KNN];
    __shared__ float sout[256 * 33];
    int b = blockIdx.y, n0 = blockIdx.x * 32;
    for (int e = threadIdx.x; e < 32 * KNN; e += blockDim.x)
        sidx[e] = g_knn[((size_t)b * NPTS + n0) * KNN + e];
    __syncthreads();
    int o = threadIdx.x;
    float sc = gam[o] * BN_RSQ, bi = bet[o];
    const float* Yb = g_Y + (size_t)b * NPTS * 256;
    const float* Zb = g_Z + (size_t)b * NPTS * 256;
    for (int nn = 0; nn < 32; nn++) {
        float m = -FLT_MAX;
        #pragma unroll
        for (int k = 0; k < KNN; k++) {
            int j = sidx[nn * KNN + k];
            m = fmaxf(m, Yb[(size_t)j * 256 + o]);
        }
        float v = Zb[(size_t)(n0 + nn) * 256 + o] + m;
        v = lrelu(fmaf(v, sc, bi));
        sout[o * 33 + nn] = v;
    }
    __syncthreads();
    float* ob = out + (size_t)b * bstr;
    for (int e = threadIdx.x; e < Cout * 32; e += blockDim.x) {
        int oo = e >> 5, nn = e & 31;
        ob[(size_t)oo * NPTS + n0 + nn] = sout[oo * 33 + nn];
    }
}

// ---------------- conv5 (512->1024) + BN + lrelu -> g_h5 (n-major) ---------
// 128x128 tile, 8x8/thread. grid (N/128, 1024/128, B), 256 threads
__global__ void k_conv5(const float* __restrict__ W5, const float* __restrict__ gam,
                        const float* __restrict__ bet) {
    __shared__ float As[8][128];
    __shared__ float Bs[8][128];
    int b = blockIdx.z;
    int n0 = blockIdx.x * 128, o0 = blockIdx.y * 128;
    int tx = threadIdx.x & 15, ty = threadIdx.x >> 4;
    int lr = threadIdx.x & 31, lc = threadIdx.x >> 5;
    int wo = threadIdx.x >> 1, wk = (threadIdx.x & 1) * 4;   // weight-load mapping
    const float* xb = g_xcat + (size_t)b * CAT_BSTR;
    float acc[8][8] = {};
    for (int c0 = 0; c0 < 512; c0 += 8) {
        float4 av = *(const float4*)&xb[(size_t)(c0 + lc) * NPTS + n0 + lr * 4];
        float4 wv = *(const float4*)&W5[(size_t)(o0 + wo) * 512 + c0 + wk];
        *(float4*)&As[lc][lr * 4] = av;
        Bs[wk + 0][wo] = wv.x;
        Bs[wk + 1][wo] = wv.y;
        Bs[wk + 2][wo] = wv.z;
        Bs[wk + 3][wo] = wv.w;
        __syncthreads();
        #pragma unroll
        for (int kk = 0; kk < 8; kk++) {
            float a[8], bb[8];
            *(float4*)&a[0] = *(const float4*)&As[kk][ty * 8];
            *(float4*)&a[4] = *(const float4*)&As[kk][ty * 8 + 4];
            *(float4*)&bb[0] = *(const float4*)&Bs[kk][tx * 8];
            *(float4*)&bb[4] = *(const float4*)&Bs[kk][tx * 8 + 4];
            #pragma unroll
            for (int r = 0; r < 8; r++)
                #pragma unroll
                for (int s = 0; s < 8; s++)
                    acc[r][s] = fmaf(a[r], bb[s], acc[r][s]);
        }
        __syncthreads();
    }
    float sc[8], bi[8];
    #pragma unroll
    for (int s = 0; s < 8; s++) {
        int o = o0 + tx * 8 + s;
        sc[s] = gam[o] * BN_RSQ; bi[s] = bet[o];
    }
    #pragma unroll
    for (int r = 0; r < 8; r++) {
        int n = n0 + ty * 8 + r;
        float o[8];
        #pragma unroll
        for (int s = 0; s < 8; s++) o[s] = lrelu(fmaf(acc[r][s], sc[s], bi[s]));
        float* dst = &g_h5[((size_t)b * NPTS + n) * 1024 + o0 + tx * 8];
        *(float4*)&dst[0] = *(float4*)&o[0];
        *(float4*)&dst[4] = *(float4*)&o[4];
    }
}

// ---------------- global max + mean pool -> g_f (B, 2048) ------------------
__global__ void k_pool() {
    int b = blockIdx.y;
    int o = blockIdx.x * 256 + threadIdx.x;
    const float* h = g_h5 + (size_t)b * NPTS * 1024;
    float mx = -FLT_MAX, sm = 0.f;
    #pragma unroll 8
    for (int n = 0; n < NPTS; n++) {
        float v = h[(size_t)n * 1024 + o];
        mx = fmaxf(mx, v);
        sm += v;
    }
    g_f[b * 2048 + o] = mx;
    g_f[b * 2048 + 1024 + o] = sm * (1.0f / NPTS);
}

// ---------------- fc1: 2048->512, BN + lrelu -------------------------------
__global__ void k_fc1(const float* __restrict__ fw, const float* __restrict__ fb,
                      const float* __restrict__ gam, const float* __restrict__ bet) {
    int b = blockIdx.y;
    int w = threadIdx.x >> 5, lane = threadIdx.x & 31;
    int o = blockIdx.x * 8 + w;
    const float* f = g_f + b * 2048;
    const float* wr = fw + (size_t)o * 2048;
    float acc = 0.f;
    for (int c = lane; c < 2048; c += 32) acc = fmaf(f[c], wr[c], acc);
    #pragma unroll
    for (int s = 16; s > 0; s >>= 1) acc += __shfl_xor_sync(0xffffffffu, acc, s);
    if (lane == 0) {
        float v = acc + fb[o];
        v = lrelu(fmaf(v, gam[o] * BN_RSQ, bet[o]));
        g_fc1[b * 512 + o] = v;
    }
}

// ---------------- fc2: 512->256, BN (no lrelu) -> d_out --------------------
__global__ void k_fc2(const float* __restrict__ fw, const float* __restrict__ fb,
                      const float* __restrict__ gam, const float* __restrict__ bet,
                      float* __restrict__ out) {
    int b = blockIdx.y;
    int w = threadIdx.x >> 5, lane = threadIdx.x & 31;
    int o = blockIdx.x * 8 + w;
    const float* f = g_fc1 + b * 512;
    const float* wr = fw + (size_t)o * 512;
    float acc = 0.f;
    for (int c = lane; c < 512; c += 32) acc = fmaf(f[c], wr[c], acc);
    #pragma unroll
    for (int s = 16; s > 0; s >>= 1) acc += __shfl_xor_sync(0xffffffffu, acc, s);
    if (lane == 0) {
        float v = acc + fb[o];
        out[b * 256 + o] = fmaf(v, gam[o] * BN_RSQ, bet[o]);
    }
}

// ---------------- driver ---------------------------------------------------
static void run_edge(const float* feat, int C, int bstr, const float* W,
                     const float* gam, const float* bet,
                     float* out, int Cout) {
    k_xx<<<(BATCH * NPTS + 255) / 256, 256>>>(feat, C, bstr);
    k_dist_topk<<<dim3(NPTS / 64, NSPLIT, BATCH), 256>>>(feat, C, bstr);
    k_merge<<<(BATCH * NPTS + 255) / 256, 256>>>();
    k_yz<<<dim3(NPTS / 64, Cout / 64, BATCH), 256>>>(feat, W, C, Cout, bstr);
    k_gather<<<dim3(NPTS / 32, BATCH), Cout>>>(out, gam, bet, Cout, CAT_BSTR);
}

extern "C" void kernel_launch(void* const* d_in, const int* in_sizes, int n_in,
                              void* d_out, int out_size) {
    const float* pts = (const float*)d_in[0];
    const float* w1 = (const float*)d_in[1];
    const float* g1 = (const float*)d_in[2];
    const float* b1 = (const float*)d_in[3];
    const float* w2 = (const float*)d_in[4];
    const float* g2 = (const float*)d_in[5];
    const float* b2 = (const float*)d_in[6];
    const float* w3 = (const float*)d_in[7];
    const float* g3 = (const float*)d_in[8];
    const float* b3 = (const float*)d_in[9];
    const float* w4 = (const float*)d_in[10];
    const float* g4 = (const float*)d_in[11];
    const float* b4 = (const float*)d_in[12];
    const float* w5 = (const float*)d_in[13];
    const float* g5 = (const float*)d_in[14];
    const float* b5 = (const float*)d_in[15];
    const float* fw1 = (const float*)d_in[16];
    const float* fb1 = (const float*)d_in[17];
    const float* g6 = (const float*)d_in[18];
    const float* b6 = (const float*)d_in[19];
    const float* fw2 = (const float*)d_in[20];
    const float* fb2 = (const float*)d_in[21];
    const float* g7 = (const float*)d_in[22];
    const float* b7 = (const float*)d_in[23];

    float *x0, *xcat;
    cudaGetSymbolAddress((void**)&x0, g_x0);
    cudaGetSymbolAddress((void**)&xcat, g_xcat);
    float* x1 = xcat;                  // ch 0..63
    float* x2 = xcat + 64 * NPTS;      // ch 64..127
    float* x3 = xcat + 128 * NPTS;     // ch 128..255
    float* x4 = xcat + 256 * NPTS;     // ch 256..511

    k_transpose<<<(BATCH * NPTS + 255) / 256, 256>>>(pts);
    run_edge(x0, 3,   3 * NPTS,  w1, g1, b1, x1, 64);
    run_edge(x1, 64,  CAT_BSTR,  w2, g2, b2, x2, 64);
    run_edge(x2, 64,  CAT_BSTR,  w3, g3, b3, x3, 128);
    run_edge(x3, 128, CAT_BSTR,  w4, g4, b4, x4, 256);
    k_conv5<<<dim3(NPTS / 128, 1024 / 128, BATCH), 256>>>(w5, g5, b5);
    k_pool<<<dim3(1024 / 256, BATCH), 256>>>();
    k_fc1<<<dim3(512 / 8, BATCH), 256>>>(fw1, fb1, g6, b6);
    k_fc2<<<dim3(256 / 8, BATCH), 256>>>(fw2, fb2, g7, b7, (float*)d_out);
}

// round 7
// speedup vs baseline: 1.8166x; 1.8166x over previous
#include <cuda_runtime.h>
#include <cfloat>
#include <cstddef>

#define NPTS 2048
#define BATCH 4
#define KNN 20
#define CAP 256

// ---------------- scratch (device globals; no allocation allowed) ----------
__device__ float g_x0[BATCH * 3 * NPTS];
// concat feature buffer: (B, 512, N). x1 @ ch 0, x2 @ 64, x3 @ 128, x4 @ 256
__device__ float g_xcat[(size_t)BATCH * 512 * NPTS];
__device__ float g_xx[BATCH * NPTS];
__device__ float g_D[(size_t)BATCH * NPTS * NPTS];       // 64 MB (L2-resident)
__device__ int   g_knn[BATCH * NPTS * KNN];
__device__ float g_cv[(size_t)BATCH * NPTS * CAP];       // candidate values
__device__ int   g_ci[(size_t)BATCH * NPTS * CAP];       // candidate indices
__device__ int   g_cnt[BATCH * NPTS];
__device__ float g_Y[BATCH * NPTS * 256];                // n-major, stride 256
__device__ float g_Z[BATCH * NPTS * 256];
__device__ float g_h5[(size_t)BATCH * NPTS * 1024];      // 32 MB
__device__ float g_f[BATCH * 2048];
__device__ float g_fc1[BATCH * 512];

__device__ __forceinline__ float lrelu(float v) { return v > 0.f ? v : 0.2f * v; }
#define BN_RSQ 0.99999500003749968750f  /* rsqrt(1+1e-5) */
#define CAT_BSTR (512 * NPTS)

// ---------------- transpose points (B,N,3) -> (B,3,N) ----------------------
__global__ void k_transpose(const float* __restrict__ pts) {
    int i = blockIdx.x * blockDim.x + threadIdx.x;
    if (i < BATCH * NPTS) {
        int b = i / NPTS, n = i % NPTS;
        #pragma unroll
        for (int c = 0; c < 3; c++)
            g_x0[(b * 3 + c) * NPTS + n] = pts[(b * NPTS + n) * 3 + c];
    }
}

// ---------------- row norms ------------------------------------------------
__global__ void k_xx(const float* __restrict__ feat, int C, int bstr) {
    int i = blockIdx.x * blockDim.x + threadIdx.x;
    if (i < BATCH * NPTS) {
        int b = i / NPTS, n = i % NPTS;
        const float* f = feat + (size_t)b * bstr + n;
        float s = 0.f;
        for (int c = 0; c < C; c++) { float v = f[(size_t)c * NPTS]; s = fmaf(v, v, s); }
        g_xx[i] = s;
    }
}

// ---------------- distance GEMM: D = 2 X^T X - xx_i - xx_j -----------------
// 128x128 tile, 8x8 per thread, K-step 8. grid (N/128, N/128, B), 256 thr.
__global__ void k_dist(const float* __restrict__ feat, int C, int bstr) {
    __shared__ float As[8][128];
    __shared__ float Bs[8][128];
    int b = blockIdx.z;
    int i0 = blockIdx.y * 128, j0 = blockIdx.x * 128;
    const float* fb = feat + (size_t)b * bstr;
    int tx = threadIdx.x & 15, ty = threadIdx.x >> 4;
    int lr = threadIdx.x & 31, lc = threadIdx.x >> 5;   // load: col-group, k-row
    float acc[8][8] = {};
    for (int c0 = 0; c0 < C; c0 += 8) {
        int c = c0 + lc;
        float4 av = {0.f, 0.f, 0.f, 0.f}, bv = {0.f, 0.f, 0.f, 0.f};
        if (c < C) {
            av = *(const float4*)&fb[(size_t)c * NPTS + i0 + lr * 4];
            bv = *(const float4*)&fb[(size_t)c * NPTS + j0 + lr * 4];
        }
        *(float4*)&As[lc][lr * 4] = av;
        *(float4*)&Bs[lc][lr * 4] = bv;
        __syncthreads();
        #pragma unroll
        for (int kk = 0; kk < 8; kk++) {
            float a[8], bb[8];
            *(float4*)&a[0] = *(const float4*)&As[kk][ty * 8];
            *(float4*)&a[4] = *(const float4*)&As[kk][ty * 8 + 4];
            *(float4*)&bb[0] = *(const float4*)&Bs[kk][tx * 8];
            *(float4*)&bb[4] = *(const float4*)&Bs[kk][tx * 8 + 4];
            #pragma unroll
            for (int r = 0; r < 8; r++)
                #pragma unroll
                for (int s = 0; s < 8; s++)
                    acc[r][s] = fmaf(a[r], bb[s], acc[r][s]);
        }
        __syncthreads();
    }
    float xj[8];
    #pragma unroll
    for (int s = 0; s < 8; s++) xj[s] = g_xx[b * NPTS + j0 + tx * 8 + s];
    #pragma unroll
    for (int r = 0; r < 8; r++) {
        int i = i0 + ty * 8 + r;
        float xi = g_xx[b * NPTS + i];
        float o[8];
        #pragma unroll
        for (int s = 0; s < 8; s++) o[s] = 2.f * acc[r][s] - xi - xj[s];
        float* dst = &g_D[((size_t)b * NPTS + i) * NPTS + j0 + tx * 8];
        *(float4*)&dst[0] = *(float4*)&o[0];
        *(float4*)&dst[4] = *(float4*)&o[4];
    }
}

// ---------------- top-K stage 1: threshold + compact -----------------------
// warp/row. Te = 20th largest of per-lane maxes (<= true 20th largest):
// the top-20 lane-maxes are 20 distinct elements all >= it. Then ballot-
// compact all v >= Te (includes every possible top-20 member incl. ties)
// into g_cv/g_ci. Branch-free; cnt is warp-uniform.
__global__ void k_topk_compact() {
    const unsigned FULL = 0xffffffffu;
    int lane = threadIdx.x & 31, warp = threadIdx.x >> 5;
    int row = blockIdx.x * 8 + warp;
    const float* drow = g_D + (size_t)row * NPTS;

    // per-lane max over its 64 elements
    float v1 = -FLT_MAX;
    #pragma unroll
    for (int t = 0; t < NPTS / 128; t++) {
        float4 q = *(const float4*)&drow[t * 128 + lane * 4];
        v1 = fmaxf(v1, fmaxf(fmaxf(q.x, q.y), fmaxf(q.z, q.w)));
    }
    // warp bitonic sort (descending) of the 32 lane maxes
    float v = v1;
    #pragma unroll
    for (int k = 2; k <= 32; k <<= 1) {
        #pragma unroll
        for (int j = k >> 1; j > 0; j >>= 1) {
            float o = __shfl_xor_sync(FULL, v, j);
            bool takeMax = (((lane & k) == 0) == ((lane & j) == 0));
            v = takeMax ? fmaxf(v, o) : fminf(v, o);
        }
    }
    float Te = __shfl_sync(FULL, v, KNN - 1);

    // compact survivors (v >= Te) -> gmem, warp-aggregated positions
    float* cv = g_cv + (size_t)row * CAP;
    int*   ci = g_ci + (size_t)row * CAP;
    unsigned lmask = (1u << lane) - 1u;
    unsigned cnt = 0;
    #pragma unroll 2
    for (int t = 0; t < NPTS / 128; t++) {
        int jb = t * 128 + lane * 4;
        float4 q = *(const float4*)&drow[jb];
        float vals[4] = {q.x, q.y, q.z, q.w};
        #pragma unroll
        for (int m = 0; m < 4; m++) {
            bool pass = vals[m] >= Te;
            unsigned mk = __ballot_sync(FULL, pass);
            if (pass) {
                unsigned pos = cnt + __popc(mk & lmask);
                if (pos < CAP) { cv[pos] = vals[m]; ci[pos] = jb + m; }
            }
            cnt += __popc(mk);
        }
    }
    if (lane == 0) g_cnt[row] = (int)cnt;
}

// ---------------- top-K stage 2: exact select (warp/row) -------------------
// Candidates distributed <=8/lane; 20 warp-argmax pops, (value desc, index
// asc) tie-break -> exact jax.lax.top_k order. Fallback full-row scan for
// cnt > CAP (degenerate mass ties; never in practice).
__global__ void k_topk_select() {
    const unsigned FULL = 0xffffffffu;
    int lane = threadIdx.x & 31, warp = threadIdx.x >> 5;
    int row = blockIdx.x * 8 + warp;
    int cnt = g_cnt[row];

    if (cnt <= CAP) {
        const float* cv = g_cv + (size_t)row * CAP;
        const int*   ci = g_ci + (size_t)row * CAP;
        float lv[8]; int li[8];
        #pragma unroll
        for (int q = 0; q < 8; q++) {
            int p = q * 32 + lane;
            bool in = p < cnt;
            lv[q] = in ? __ldg(&cv[p]) : -FLT_MAX;
            li[q] = in ? __ldg(&ci[p]) : 0x7FFFFFFF;
        }
        #pragma unroll 1
        for (int k = 0; k < KNN; k++) {
            float bv = -FLT_MAX; int bi = 0x7FFFFFFF, bq = 0;
            #pragma unroll
            for (int q = 0; q < 8; q++) {
                if (lv[q] > bv || (lv[q] == bv && li[q] < bi)) {
                    bv = lv[q]; bi = li[q]; bq = q;
                }
            }
            float wv = bv; int wi = bi;
            #pragma unroll
            for (int s = 16; s > 0; s >>= 1) {
                float ov = __shfl_xor_sync(FULL, wv, s);
                int   oi = __shfl_xor_sync(FULL, wi, s);
                if (ov > wv || (ov == wv && oi < wi)) { wv = ov; wi = oi; }
            }
            if (lane == 0) g_knn[(size_t)row * KNN + k] = wi;
            if (bv == wv && bi == wi) {        // unique: indices distinct
                lv[bq] = -FLT_MAX; li[bq] = 0x7FFFFFFF;
            }
        }
    } else {
        // exact fallback: full-row scan, per-lane sorted 20-list + 20 pops
        const float* drow = g_D + (size_t)row * NPTS;
        float arr[KNN]; int ai[KNN];
        #pragma unroll
        for (int q = 0; q < KNN; q++) { arr[q] = -FLT_MAX; ai[q] = 0x7FFFFFFF; }
        #pragma unroll 1
        for (int t = 0; t < NPTS / 128; t++) {
            int jb = t * 128 + lane * 4;
            float4 v4 = *(const float4*)&drow[jb];
            float vv[4] = {v4.x, v4.y, v4.z, v4.w};
            #pragma unroll
            for (int m = 0; m < 4; m++) {
                float vx = vv[m];
                if (vx > arr[0]) {             // ascending j: strict > keeps earlier
                    arr[0] = vx; ai[0] = jb + m;
                    #pragma unroll
                    for (int q = 0; q < KNN - 1; q++) {
                        if (arr[q + 1] < arr[q]) {
                            float tv = arr[q]; arr[q] = arr[q + 1]; arr[q + 1] = tv;
                            int ti = ai[q]; ai[q] = ai[q + 1]; ai[q + 1] = ti;
                        }
                    }
                }
            }
        }
        #pragma unroll 1
        for (int k = 0; k < KNN; k++) {
            float cvv = arr[KNN - 1]; int cii = ai[KNN - 1];
            float wv = cvv; int wi = cii;
            #pragma unroll
            for (int s = 16; s > 0; s >>= 1) {
                float ov = __shfl_xor_sync(FULL, wv, s);
                int   oi = __shfl_xor_sync(FULL, wi, s);
                if (ov > wv || (ov == wv && oi < wi)) { wv = ov; wi = oi; }
            }
            if (lane == 0) g_knn[(size_t)row * KNN + k] = wi;
            if (cii == wi) {
                #pragma unroll
                for (int q = KNN - 1; q > 0; q--) { arr[q] = arr[q - 1]; ai[q] = ai[q - 1]; }
                arr[0] = -FLT_MAX; ai[0] = 0x7FFFFFFF;
            }
        }
    }
}

// ---------------- Y = W2 X, Z = (W1-W2) X ; stored n-major stride 256 ------
// grid (N/64, Cout/64, B), 256 threads
__global__ void k_yz(const float* __restrict__ feat, const float* __restrict__ W,
                     int C, int Cout, int bstr) {
    __shared__ float As[16][64];
    __shared__ float B1[16][64];
    __shared__ float B2[16][64];
    int b = blockIdx.z;
    int n0 = blockIdx.x * 64, o0 = blockIdx.y * 64;
    const float* fb = feat + (size_t)b * bstr;
    int tx = threadIdx.x & 15, ty = threadIdx.x >> 4;
    float aU[4][4] = {}, aY[4][4] = {};
    for (int c0 = 0; c0 < C; c0 += 16) {
        for (int e = threadIdx.x; e < 1024; e += 256) {
            int kk = e >> 6, nn = e & 63;
            int c = c0 + kk;
            As[kk][nn] = (c < C) ? fb[(size_t)c * NPTS + n0 + nn] : 0.f;
        }
        for (int e = threadIdx.x; e < 1024; e += 256) {
            int kk = e & 15, oo = e >> 4;
            int c = c0 + kk;
            float w1 = 0.f, w2 = 0.f;
            if (c < C) {
                const float* wr = W + (size_t)(o0 + oo) * (2 * C);
                w1 = wr[c]; w2 = wr[C + c];
            }
            B1[kk][oo] = w1; B2[kk][oo] = w2;
        }
        __syncthreads();
        #pragma unroll
        for (int kk = 0; kk < 16; kk++) {
            float4 a4 = *(const float4*)&As[kk][ty * 4];
            float4 b14 = *(const float4*)&B1[kk][tx * 4];
            float4 b24 = *(const float4*)&B2[kk][tx * 4];
            float av[4] = {a4.x, a4.y, a4.z, a4.w};
            float b1v[4] = {b14.x, b14.y, b14.z, b14.w};
            float b2v[4] = {b24.x, b24.y, b24.z, b24.w};
            #pragma unroll
            for (int r = 0; r < 4; r++)
                #pragma unroll
                for (int s = 0; s < 4; s++) {
                    aU[r][s] = fmaf(av[r], b1v[s], aU[r][s]);
                    aY[r][s] = fmaf(av[r], b2v[s], aY[r][s]);
                }
        }
        __syncthreads();
    }
    #pragma unroll
    for (int r = 0; r < 4; r++) {
        int n = n0 + ty * 4 + r;
        size_t base = ((size_t)b * NPTS + n) * 256 + o0 + tx * 4;
        float4 y, z;
        y.x = aY[r][0]; y.y = aY[r][1]; y.z = aY[r][2]; y.w = aY[r][3];
        z.x = aU[r][0] - y.x; z.y = aU[r][1] - y.y;
        z.z = aU[r][2] - y.z; z.w = aU[r][3] - y.w;
        *(float4*)&g_Y[base] = y;
        *(float4*)&g_Z[base] = z;
    }
}

// ---------------- gather-max + BN + lrelu -> out slice of g_xcat -----------
// grid (N/32, B), blockDim = Cout
__global__ void k_gather(float* __restrict__ out, const float* __restrict__ gam,
                         const float* __restrict__ bet, int Cout, int bstr) {
    __shared__ int   sidx[32 * KNN];
    __shared__ float sout[256 * 33];
    int b = blockIdx.y, n0 = blockIdx.x * 32;
    for (int e = threadIdx.x; e < 32 * KNN; e += blockDim.x)
        sidx[e] = g_knn[((size_t)b * NPTS + n0) * KNN + e];
    __syncthreads();
    int o = threadIdx.x;
    float sc = gam[o] * BN_RSQ, bi = bet[o];
    const float* Yb = g_Y + (size_t)b * NPTS * 256;
    const float* Zb = g_Z + (size_t)b * NPTS * 256;
    for (int nn = 0; nn < 32; nn++) {
        float m = -FLT_MAX;
        #pragma unroll
        for (int k = 0; k < KNN; k++) {
            int j = sidx[nn * KNN + k];
            m = fmaxf(m, Yb[(size_t)j * 256 + o]);
        }
        float v = Zb[(size_t)(n0 + nn) * 256 + o] + m;
        v = lrelu(fmaf(v, sc, bi));
        sout[o * 33 + nn] = v;
    }
    __syncthreads();
    float* ob = out + (size_t)b * bstr;
    for (int e = threadIdx.x; e < Cout * 32; e += blockDim.x) {
        int oo = e >> 5, nn = e & 31;
        ob[(size_t)oo * NPTS + n0 + nn] = sout[oo * 33 + nn];
    }
}

// ---------------- conv5 (512->1024) + BN + lrelu -> g_h5 (n-major) ---------
// 128x128 tile, 8x8/thread. grid (N/128, 1024/128, B), 256 threads
__global__ void k_conv5(const float* __restrict__ W5, const float* __restrict__ gam,
                        const float* __restrict__ bet) {
    __shared__ float As[8][128];
    __shared__ float Bs[8][128];
    int b = blockIdx.z;
    int n0 = blockIdx.x * 128, o0 = blockIdx.y * 128;
    int tx = threadIdx.x & 15, ty = threadIdx.x >> 4;
    int lr = threadIdx.x & 31, lc = threadIdx.x >> 5;
    int wo = threadIdx.x >> 1, wk = (threadIdx.x & 1) * 4;   // weight-load mapping
    const float* xb = g_xcat + (size_t)b * CAT_BSTR;
    float acc[8][8] = {};
    for (int c0 = 0; c0 < 512; c0 += 8) {
        float4 av = *(const float4*)&xb[(size_t)(c0 + lc) * NPTS + n0 + lr * 4];
        float4 wv = *(const float4*)&W5[(size_t)(o0 + wo) * 512 + c0 + wk];
        *(float4*)&As[lc][lr * 4] = av;
        Bs[wk + 0][wo] = wv.x;
        Bs[wk + 1][wo] = wv.y;
        Bs[wk + 2][wo] = wv.z;
        Bs[wk + 3][wo] = wv.w;
        __syncthreads();
        #pragma unroll
        for (int kk = 0; kk < 8; kk++) {
            float a[8], bb[8];
            *(float4*)&a[0] = *(const float4*)&As[kk][ty * 8];
            *(float4*)&a[4] = *(const float4*)&As[kk][ty * 8 + 4];
            *(float4*)&bb[0] = *(const float4*)&Bs[kk][tx * 8];
            *(float4*)&bb[4] = *(const float4*)&Bs[kk][tx * 8 + 4];
            #pragma unroll
            for (int r = 0; r < 8; r++)
                #pragma unroll
                for (int s = 0; s < 8; s++)
                    acc[r][s] = fmaf(a[r], bb[s], acc[r][s]);
        }
        __syncthreads();
    }
    float sc[8], bi[8];
    #pragma unroll
    for (int s = 0; s < 8; s++) {
        int o = o0 + tx * 8 + s;
        sc[s] = gam[o] * BN_RSQ; bi[s] = bet[o];
    }
    #pragma unroll
    for (int r = 0; r < 8; r++) {
        int n = n0 + ty * 8 + r;
        float o[8];
        #pragma unroll
        for (int s = 0; s < 8; s++) o[s] = lrelu(fmaf(acc[r][s], sc[s], bi[s]));
        float* dst = &g_h5[((size_t)b * NPTS + n) * 1024 + o0 + tx * 8];
        *(float4*)&dst[0] = *(float4*)&o[0];
        *(float4*)&dst[4] = *(float4*)&o[4];
    }
}

// ---------------- global max + mean pool -> g_f (B, 2048) ------------------
__global__ void k_pool() {
    int b = blockIdx.y;
    int o = blockIdx.x * 256 + threadIdx.x;
    const float* h = g_h5 + (size_t)b * NPTS * 1024;
    float mx = -FLT_MAX, sm = 0.f;
    #pragma unroll 8
    for (int n = 0; n < NPTS; n++) {
        float v = h[(size_t)n * 1024 + o];
        mx = fmaxf(mx, v);
        sm += v;
    }
    g_f[b * 2048 + o] = mx;
    g_f[b * 2048 + 1024 + o] = sm * (1.0f / NPTS);
}

// ---------------- fc1: 2048->512, BN + lrelu -------------------------------
__global__ void k_fc1(const float* __restrict__ fw, const float* __restrict__ fb,
                      const float* __restrict__ gam, const float* __restrict__ bet) {
    int b = blockIdx.y;
    int w = threadIdx.x >> 5, lane = threadIdx.x & 31;
    int o = blockIdx.x * 8 + w;
    const float* f = g_f + b * 2048;
    const float* wr = fw + (size_t)o * 2048;
    float acc = 0.f;
    for (int c = lane; c < 2048; c += 32) acc = fmaf(f[c], wr[c], acc);
    #pragma unroll
    for (int s = 16; s > 0; s >>= 1) acc += __shfl_xor_sync(0xffffffffu, acc, s);
    if (lane == 0) {
        float v = acc + fb[o];
        v = lrelu(fmaf(v, gam[o] * BN_RSQ, bet[o]));
        g_fc1[b * 512 + o] = v;
    }
}

// ---------------- fc2: 512->256, BN (no lrelu) -> d_out --------------------
__global__ void k_fc2(const float* __restrict__ fw, const float* __restrict__ fb,
                      const float* __restrict__ gam, const float* __restrict__ bet,
                      float* __restrict__ out) {
    int b = blockIdx.y;
    int w = threadIdx.x >> 5, lane = threadIdx.x & 31;
    int o = blockIdx.x * 8 + w;
    const float* f = g_fc1 + b * 512;
    const float* wr = fw + (size_t)o * 512;
    float acc = 0.f;
    for (int c = lane; c < 512; c += 32) acc = fmaf(f[c], wr[c], acc);
    #pragma unroll
    for (int s = 16; s > 0; s >>= 1) acc += __shfl_xor_sync(0xffffffffu, acc, s);
    if (lane == 0) {
        float v = acc + fb[o];
        out[b * 256 + o] = fmaf(v, gam[o] * BN_RSQ, bet[o]);
    }
}

// ---------------- driver ---------------------------------------------------
static void run_edge(const float* feat, int C, int bstr, const float* W,
                     const float* gam, const float* bet,
                     float* out, int Cout) {
    k_xx<<<(BATCH * NPTS + 255) / 256, 256>>>(feat, C, bstr);
    k_dist<<<dim3(NPTS / 128, NPTS / 128, BATCH), 256>>>(feat, C, bstr);
    k_topk_compact<<<BATCH * NPTS / 8, 256>>>();
    k_topk_select<<<BATCH * NPTS / 8, 256>>>();
    k_yz<<<dim3(NPTS / 64, Cout / 64, BATCH), 256>>>(feat, W, C, Cout, bstr);
    k_gather<<<dim3(NPTS / 32, BATCH), Cout>>>(out, gam, bet, Cout, CAT_BSTR);
}

extern "C" void kernel_launch(void* const* d_in, const int* in_sizes, int n_in,
                              void* d_out, int out_size) {
    const float* pts = (const float*)d_in[0];
    const float* w1 = (const float*)d_in[1];
    const float* g1 = (const float*)d_in[2];
    const float* b1 = (const float*)d_in[3];
    const float* w2 = (const float*)d_in[4];
    const float* g2 = (const float*)d_in[5];
    const float* b2 = (const float*)d_in[6];
    const float* w3 = (const float*)d_in[7];
    const float* g3 = (const float*)d_in[8];
    const float* b3 = (const float*)d_in[9];
    const float* w4 = (const float*)d_in[10];
    const float* g4 = (const float*)d_in[11];
    const float* b4 = (const float*)d_in[12];
    const float* w5 = (const float*)d_in[13];
    const float* g5 = (const float*)d_in[14];
    const float* b5 = (const float*)d_in[15];
    const float* fw1 = (const float*)d_in[16];
    const float* fb1 = (const float*)d_in[17];
    const float* g6 = (const float*)d_in[18];
    const float* b6 = (const float*)d_in[19];
    const float* fw2 = (const float*)d_in[20];
    const float* fb2 = (const float*)d_in[21];
    const float* g7 = (const float*)d_in[22];
    const float* b7 = (const float*)d_in[23];

    float *x0, *xcat;
    cudaGetSymbolAddress((void**)&x0, g_x0);
    cudaGetSymbolAddress((void**)&xcat, g_xcat);
    float* x1 = xcat;                  // ch 0..63
    float* x2 = xcat + 64 * NPTS;      // ch 64..127
    float* x3 = xcat + 128 * NPTS;     // ch 128..255
    float* x4 = xcat + 256 * NPTS;     // ch 256..511

    k_transpose<<<(BATCH * NPTS + 255) / 256, 256>>>(pts);
    run_edge(x0, 3,   3 * NPTS,  w1, g1, b1, x1, 64);
    run_edge(x1, 64,  CAT_BSTR,  w2, g2, b2, x2, 64);
    run_edge(x2, 64,  CAT_BSTR,  w3, g3, b3, x3, 128);
    run_edge(x3, 128, CAT_BSTR,  w4, g4, b4, x4, 256);
    k_conv5<<<dim3(NPTS / 128, 1024 / 128, BATCH), 256>>>(w5, g5, b5);
    k_pool<<<dim3(1024 / 256, BATCH), 256>>>();
    k_fc1<<<dim3(512 / 8, BATCH), 256>>>(fw1, fb1, g6, b6);
    k_fc2<<<dim3(256 / 8, BATCH), 256>>>(fw2, fb2, g7, b7, (float*)d_out);
}

// round 8
// speedup vs baseline: 2.0317x; 1.1185x over previous
#include <cuda_runtime.h>
#include <cuda_bf16.h>
#include <cfloat>
#include <cstdint>
#include <cstddef>

#define NPTS 2048
#define BATCH 4
#define KNN 20
#define CAP 256

// ---------------- scratch (device globals; no allocation allowed) ----------
__device__ float g_x0[BATCH * 3 * NPTS];
__device__ float g_xcat[(size_t)BATCH * 512 * NPTS];     // fp32 concat feats
__device__ uint16_t g_x0h[BATCH * 16 * NPTS];            // bf16 hi of x0, Cpad=16
__device__ uint16_t g_x0l[BATCH * 16 * NPTS];            // bf16 lo
__device__ uint16_t g_ch[(size_t)BATCH * 512 * NPTS];    // bf16 hi of xcat
__device__ uint16_t g_cl[(size_t)BATCH * 512 * NPTS];    // bf16 lo
__device__ uint16_t g_w5h[1024 * 512];
__device__ uint16_t g_w5l[1024 * 512];
__device__ float g_xx[BATCH * NPTS];
__device__ float g_D[(size_t)BATCH * NPTS * NPTS];       // 64 MB
__device__ int   g_knn[BATCH * NPTS * KNN];
__device__ float g_cv[(size_t)BATCH * NPTS * CAP];
__device__ int   g_ci[(size_t)BATCH * NPTS * CAP];
__device__ int   g_cnt[BATCH * NPTS];
__device__ float g_Y[BATCH * NPTS * 256];
__device__ float g_Z[BATCH * NPTS * 256];
__device__ float g_h5[(size_t)BATCH * NPTS * 1024];
__device__ float g_f[BATCH * 2048];
__device__ float g_fc1[BATCH * 512];

__device__ __forceinline__ float lrelu(float v) { return v > 0.f ? v : 0.2f * v; }
#define BN_RSQ 0.99999500003749968750f
#define CAT_BSTR (512 * NPTS)
#define LDK 18   /* smem tile row stride in halves */

__device__ __forceinline__ void split_bf16(float x, uint16_t& h, uint16_t& l) {
    __nv_bfloat16 bh = __float2bfloat16(x);
    float r = x - __bfloat162float(bh);
    __nv_bfloat16 bl = __float2bfloat16(r);
    h = *reinterpret_cast<uint16_t*>(&bh);
    l = *reinterpret_cast<uint16_t*>(&bl);
}

__device__ __forceinline__ void mma_bf16(float c[4], const uint32_t a[4],
                                         uint32_t b0, uint32_t b1) {
    asm volatile(
        "mma.sync.aligned.m16n8k16.row.col.f32.bf16.bf16.f32 "
        "{%0,%1,%2,%3}, {%4,%5,%6,%7}, {%8,%9}, {%0,%1,%2,%3};"
        : "+f"(c[0]), "+f"(c[1]), "+f"(c[2]), "+f"(c[3])
        : "r"(a[0]), "r"(a[1]), "r"(a[2]), "r"(a[3]), "r"(b0), "r"(b1));
}

// ---------------- transpose points + bf16 split (Cpad=16) ------------------
__global__ void k_transpose(const float* __restrict__ pts) {
    int i = blockIdx.x * blockDim.x + threadIdx.x;
    if (i < BATCH * NPTS) {
        int b = i / NPTS, n = i % NPTS;
        #pragma unroll
        for (int c = 0; c < 3; c++) {
            float v = pts[(b * NPTS + n) * 3 + c];
            g_x0[(b * 3 + c) * NPTS + n] = v;
            uint16_t h, l;
            split_bf16(v, h, l);
            g_x0h[(b * 16 + c) * NPTS + n] = h;
            g_x0l[(b * 16 + c) * NPTS + n] = l;
        }
        #pragma unroll
        for (int c = 3; c < 16; c++) {
            g_x0h[(b * 16 + c) * NPTS + n] = 0;
            g_x0l[(b * 16 + c) * NPTS + n] = 0;
        }
    }
}

// ---------------- row norms (fp32 exact) -----------------------------------
__global__ void k_xx(const float* __restrict__ feat, int C, int bstr) {
    int i = blockIdx.x * blockDim.x + threadIdx.x;
    if (i < BATCH * NPTS) {
        int b = i / NPTS, n = i % NPTS;
        const float* f = feat + (size_t)b * bstr + n;
        float s = 0.f;
        for (int c = 0; c < C; c++) { float v = f[(size_t)c * NPTS]; s = fmaf(v, v, s); }
        g_xx[i] = s;
    }
}

// ---------------- w5 bf16 split --------------------------------------------
__global__ void k_cvt_w5(const float* __restrict__ w5) {
    int i = blockIdx.x * blockDim.x + threadIdx.x;
    if (i < 1024 * 512) {
        uint16_t h, l;
        split_bf16(w5[i], h, l);
        g_w5h[i] = h; g_w5l[i] = l;
    }
}

// ---------------- distance GEMM via split-bf16 mma -------------------------
// D = 2 X^T X - xx_i - xx_j, X^T X ~ Xh'Xh + Xl'Xh + Xh'Xl (fp32 accum).
// grid (N/128, N/128, B), 256 thr. CTA 128x128, warp 32(m)x64(n).
__global__ void k_dist_mma(const uint16_t* __restrict__ srch,
                           const uint16_t* __restrict__ srcl,
                           int Ceff, int bstr) {
    __shared__ uint16_t Ah[128 * LDK], Al[128 * LDK];
    __shared__ uint16_t Bh[128 * LDK], Bl[128 * LDK];
    int b = blockIdx.z;
    int i0 = blockIdx.y * 128, j0 = blockIdx.x * 128;
    const uint16_t* ph = srch + (size_t)b * bstr;
    const uint16_t* pl = srcl + (size_t)b * bstr;
    int tid = threadIdx.x, lane = tid & 31, warp = tid >> 5;
    int wm = warp & 3, wn = warp >> 2;
    int g = lane >> 2, t = lane & 3;
    float acc[2][8][4];
    #pragma unroll
    for (int mt = 0; mt < 2; mt++)
        #pragma unroll
        for (int nt = 0; nt < 8; nt++)
            #pragma unroll
            for (int q = 0; q < 4; q++) acc[mt][nt][q] = 0.f;

    int p = tid & 63, cs = tid >> 6;      // loader mapping: n-pair, c-phase
    for (int c0 = 0; c0 < Ceff; c0 += 16) {
        #pragma unroll
        for (int cc = cs; cc < 16; cc += 4) {
            size_t rb = (size_t)(c0 + cc) * NPTS;
            uint32_t va = *(const uint32_t*)&ph[rb + i0 + 2 * p];
            Ah[(2 * p) * LDK + cc] = (uint16_t)va;
            Ah[(2 * p + 1) * LDK + cc] = (uint16_t)(va >> 16);
            uint32_t vb = *(const uint32_t*)&ph[rb + j0 + 2 * p];
            Bh[(2 * p) * LDK + cc] = (uint16_t)vb;
            Bh[(2 * p + 1) * LDK + cc] = (uint16_t)(vb >> 16);
            uint32_t la = *(const uint32_t*)&pl[rb + i0 + 2 * p];
            Al[(2 * p) * LDK + cc] = (uint16_t)la;
            Al[(2 * p + 1) * LDK + cc] = (uint16_t)(la >> 16);
            uint32_t lb = *(const uint32_t*)&pl[rb + j0 + 2 * p];
            Bl[(2 * p) * LDK + cc] = (uint16_t)lb;
            Bl[(2 * p + 1) * LDK + cc] = (uint16_t)(lb >> 16);
        }
        __syncthreads();
        #pragma unroll 1
        for (int pass = 0; pass < 3; pass++) {
            const uint16_t* A = (pass == 1) ? Al : Ah;
            const uint16_t* B = (pass == 2) ? Bl : Bh;
            uint32_t af[2][4];
            #pragma unroll
            for (int mt = 0; mt < 2; mt++) {
                int row = wm * 32 + mt * 16;
                af[mt][0] = *(const uint32_t*)&A[(row + g) * LDK + 2 * t];
                af[mt][1] = *(const uint32_t*)&A[(row + g + 8) * LDK + 2 * t];
                af[mt][2] = *(const uint32_t*)&A[(row + g) * LDK + 2 * t + 8];
                af[mt][3] = *(const uint32_t*)&A[(row + g + 8) * LDK + 2 * t + 8];
            }
            #pragma unroll
            for (int nt = 0; nt < 8; nt++) {
                int col = wn * 64 + nt * 8;
                uint32_t b0 = *(const uint32_t*)&B[(col + g) * LDK + 2 * t];
                uint32_t b1 = *(const uint32_t*)&B[(col + g) * LDK + 2 * t + 8];
                mma_bf16(acc[0][nt], af[0], b0, b1);
                mma_bf16(acc[1][nt], af[1], b0, b1);
            }
        }
        __syncthreads();
    }
    // epilogue: 2*acc - xi - xj -> g_D
    #pragma unroll
    for (int mt = 0; mt < 2; mt++) {
        int r0 = i0 + wm * 32 + mt * 16 + g;
        int r1 = r0 + 8;
        float xi0 = g_xx[b * NPTS + r0];
        float xi1 = g_xx[b * NPTS + r1];
        #pragma unroll
        for (int nt = 0; nt < 8; nt++) {
            int j = j0 + wn * 64 + nt * 8 + 2 * t;
            float xj0 = g_xx[b * NPTS + j];
            float xj1 = g_xx[b * NPTS + j + 1];
            float2 v0, v1;
            v0.x = 2.f * acc[mt][nt][0] - xi0 - xj0;
            v0.y = 2.f * acc[mt][nt][1] - xi0 - xj1;
            v1.x = 2.f * acc[mt][nt][2] - xi1 - xj0;
            v1.y = 2.f * acc[mt][nt][3] - xi1 - xj1;
            *(float2*)&g_D[((size_t)b * NPTS + r0) * NPTS + j] = v0;
            *(float2*)&g_D[((size_t)b * NPTS + r1) * NPTS + j] = v1;
        }
    }
}

// ---------------- conv5 via split-bf16 mma + BN + lrelu --------------------
// grid (N/128, 1024/128, B), 256 thr. A = xcat (transposed tiles), B = W5.
__global__ void k_conv5_mma(const float* __restrict__ gam,
                            const float* __restrict__ bet) {
    __shared__ uint16_t Ah[128 * LDK], Al[128 * LDK];
    __shared__ uint16_t Bh[128 * LDK], Bl[128 * LDK];
    int b = blockIdx.z;
    int n0 = blockIdx.x * 128, o0 = blockIdx.y * 128;
    const uint16_t* ph = g_ch + (size_t)b * CAT_BSTR;
    const uint16_t* pl = g_cl + (size_t)b * CAT_BSTR;
    int tid = threadIdx.x, lane = tid & 31, warp = tid >> 5;
    int wm = warp & 3, wn = warp >> 2;
    int g = lane >> 2, t = lane & 3;
    float acc[2][8][4];
    #pragma unroll
    for (int mt = 0; mt < 2; mt++)
        #pragma unroll
        for (int nt = 0; nt < 8; nt++)
            #pragma unroll
            for (int q = 0; q < 4; q++) acc[mt][nt][q] = 0.f;

    int p = tid & 63, cs = tid >> 6;
    int wrow = tid >> 1, whs = (tid & 1) * 8;     // weight loader mapping
    for (int c0 = 0; c0 < 512; c0 += 16) {
        #pragma unroll
        for (int cc = cs; cc < 16; cc += 4) {
            size_t rb = (size_t)(c0 + cc) * NPTS;
            uint32_t va = *(const uint32_t*)&ph[rb + n0 + 2 * p];
            Ah[(2 * p) * LDK + cc] = (uint16_t)va;
            Ah[(2 * p + 1) * LDK + cc] = (uint16_t)(va >> 16);
            uint32_t la = *(const uint32_t*)&pl[rb + n0 + 2 * p];
            Al[(2 * p) * LDK + cc] = (uint16_t)la;
            Al[(2 * p + 1) * LDK + cc] = (uint16_t)(la >> 16);
        }
        {
            uint4 w4 = *(const uint4*)&g_w5h[(size_t)(o0 + wrow) * 512 + c0 + whs];
            uint32_t ws[4] = {w4.x, w4.y, w4.z, w4.w};
            #pragma unroll
            for (int q = 0; q < 4; q++) {
                Bh[wrow * LDK + whs + 2 * q] = (uint16_t)ws[q];
                Bh[wrow * LDK + whs + 2 * q + 1] = (uint16_t)(ws[q] >> 16);
            }
            uint4 l4 = *(const uint4*)&g_w5l[(size_t)(o0 + wrow) * 512 + c0 + whs];
            uint32_t ls[4] = {l4.x, l4.y, l4.z, l4.w};
            #pragma unroll
            for (int q = 0; q < 4; q++) {
                Bl[wrow * LDK + whs + 2 * q] = (uint16_t)ls[q];
                Bl[wrow * LDK + whs + 2 * q + 1] = (uint16_t)(ls[q] >> 16);
            }
        }
        __syncthreads();
        #pragma unroll 1
        for (int pass = 0; pass < 3; pass++) {
            const uint16_t* A = (pass == 1) ? Al : Ah;
            const uint16_t* B = (pass == 2) ? Bl : Bh;
            uint32_t af[2][4];
            #pragma unroll
            for (int mt = 0; mt < 2; mt++) {
                int row = wm * 32 + mt * 16;
                af[mt][0] = *(const uint32_t*)&A[(row + g) * LDK + 2 * t];
                af[mt][1] = *(const uint32_t*)&A[(row + g + 8) * LDK + 2 * t];
                af[mt][2] = *(const uint32_t*)&A[(row + g) * LDK + 2 * t + 8];
                af[mt][3] = *(const uint32_t*)&A[(row + g + 8) * LDK + 2 * t + 8];
            }
            #pragma unroll
            for (int nt = 0; nt < 8; nt++) {
                int col = wn * 64 + nt * 8;
                uint32_t b0 = *(const uint32_t*)&B[(col + g) * LDK + 2 * t];
                uint32_t b1 = *(const uint32_t*)&B[(col + g) * LDK + 2 * t + 8];
                mma_bf16(acc[0][nt], af[0], b0, b1);
                mma_bf16(acc[1][nt], af[1], b0, b1);
            }
        }
        __syncthreads();
    }
    // epilogue: BN + lrelu -> g_h5 (n-major)
    #pragma unroll
    for (int mt = 0; mt < 2; mt++) {
        int r0 = n0 + wm * 32 + mt * 16 + g;
        int r1 = r0 + 8;
        #pragma unroll
        for (int nt = 0; nt < 8; nt++) {
            int o = o0 + wn * 64 + nt * 8 + 2 * t;
            float sc0 = gam[o] * BN_RSQ, bi0 = bet[o];
            float sc1 = gam[o + 1] * BN_RSQ, bi1 = bet[o + 1];
            float2 v0, v1;
            v0.x = lrelu(fmaf(acc[mt][nt][0], sc0, bi0));
            v0.y = lrelu(fmaf(acc[mt][nt][1], sc1, bi1));
            v1.x = lrelu(fmaf(acc[mt][nt][2], sc0, bi0));
            v1.y = lrelu(fmaf(acc[mt][nt][3], sc1, bi1));
            *(float2*)&g_h5[((size_t)b * NPTS + r0) * 1024 + o] = v0;
            *(float2*)&g_h5[((size_t)b * NPTS + r1) * 1024 + o] = v1;
        }
    }
}

// ---------------- top-K stage 1: threshold + compact -----------------------
__global__ void k_topk_compact() {
    const unsigned FULL = 0xffffffffu;
    int lane = threadIdx.x & 31, warp = threadIdx.x >> 5;
    int row = blockIdx.x * 8 + warp;
    const float* drow = g_D + (size_t)row * NPTS;

    float v1 = -FLT_MAX;
    #pragma unroll
    for (int t = 0; t < NPTS / 128; t++) {
        float4 q = *(const float4*)&drow[t * 128 + lane * 4];
        v1 = fmaxf(v1, fmaxf(fmaxf(q.x, q.y), fmaxf(q.z, q.w)));
    }
    float v = v1;
    #pragma unroll
    for (int k = 2; k <= 32; k <<= 1) {
        #pragma unroll
        for (int j = k >> 1; j > 0; j >>= 1) {
            float o = __shfl_xor_sync(FULL, v, j);
            bool takeMax = (((lane & k) == 0) == ((lane & j) == 0));
            v = takeMax ? fmaxf(v, o) : fminf(v, o);
        }
    }
    float Te = __shfl_sync(FULL, v, KNN - 1);

    float* cv = g_cv + (size_t)row * CAP;
    int*   ci = g_ci + (size_t)row * CAP;
    unsigned lmask = (1u << lane) - 1u;
    unsigned cnt = 0;
    #pragma unroll 2
    for (int t = 0; t < NPTS / 128; t++) {
        int jb = t * 128 + lane * 4;
        float4 q = *(const float4*)&drow[jb];
        float vals[4] = {q.x, q.y, q.z, q.w};
        #pragma unroll
        for (int m = 0; m < 4; m++) {
            bool pass = vals[m] >= Te;
            unsigned mk = __ballot_sync(FULL, pass);
            if (pass) {
                unsigned pos = cnt + __popc(mk & lmask);
                if (pos < CAP) { cv[pos] = vals[m]; ci[pos] = jb + m; }
            }
            cnt += __popc(mk);
        }
    }
    if (lane == 0) g_cnt[row] = (int)cnt;
}

// ---------------- top-K stage 2: exact select ------------------------------
__global__ void k_topk_select() {
    const unsigned FULL = 0xffffffffu;
    int lane = threadIdx.x & 31, warp = threadIdx.x >> 5;
    int row = blockIdx.x * 8 + warp;
    int cnt = g_cnt[row];

    if (cnt <= CAP) {
        const float* cv = g_cv + (size_t)row * CAP;
        const int*   ci = g_ci + (size_t)row * CAP;
        float lv[8]; int li[8];
        #pragma unroll
        for (int q = 0; q < 8; q++) {
            int p = q * 32 + lane;
            bool in = p < cnt;
            lv[q] = in ? __ldg(&cv[p]) : -FLT_MAX;
            li[q] = in ? __ldg(&ci[p]) : 0x7FFFFFFF;
        }
        #pragma unroll 1
        for (int k = 0; k < KNN; k++) {
            float bv = -FLT_MAX; int bi = 0x7FFFFFFF, bq = 0;
            #pragma unroll
            for (int q = 0; q < 8; q++) {
                if (lv[q] > bv || (lv[q] == bv && li[q] < bi)) {
                    bv = lv[q]; bi = li[q]; bq = q;
                }
            }
            float wv = bv; int wi = bi;
            #pragma unroll
            for (int s = 16; s > 0; s >>= 1) {
                float ov = __shfl_xor_sync(FULL, wv, s);
                int   oi = __shfl_xor_sync(FULL, wi, s);
                if (ov > wv || (ov == wv && oi < wi)) { wv = ov; wi = oi; }
            }
            if (lane == 0) g_knn[(size_t)row * KNN + k] = wi;
            if (bv == wv && bi == wi) { lv[bq] = -FLT_MAX; li[bq] = 0x7FFFFFFF; }
        }
    } else {
        const float* drow = g_D + (size_t)row * NPTS;
        float arr[KNN]; int ai[KNN];
        #pragma unroll
        for (int q = 0; q < KNN; q++) { arr[q] = -FLT_MAX; ai[q] = 0x7FFFFFFF; }
        #pragma unroll 1
        for (int t = 0; t < NPTS / 128; t++) {
            int jb = t * 128 + lane * 4;
            float4 v4 = *(const float4*)&drow[jb];
            float vv[4] = {v4.x, v4.y, v4.z, v4.w};
            #pragma unroll
            for (int m = 0; m < 4; m++) {
                float vx = vv[m];
                if (vx > arr[0]) {
                    arr[0] = vx; ai[0] = jb + m;
                    #pragma unroll
                    for (int q = 0; q < KNN - 1; q++) {
                        if (arr[q + 1] < arr[q]) {
                            float tv = arr[q]; arr[q] = arr[q + 1]; arr[q + 1] = tv;
                            int ti = ai[q]; ai[q] = ai[q + 1]; ai[q + 1] = ti;
                        }
                    }
                }
            }
        }
        #pragma unroll 1
        for (int k = 0; k < KNN; k++) {
            float cvv = arr[KNN - 1]; int cii = ai[KNN - 1];
            float wv = cvv; int wi = cii;
            #pragma unroll
            for (int s = 16; s > 0; s >>= 1) {
                float ov = __shfl_xor_sync(FULL, wv, s);
                int   oi = __shfl_xor_sync(FULL, wi, s);
                if (ov > wv || (ov == wv && oi < wi)) { wv = ov; wi = oi; }
            }
            if (lane == 0) g_knn[(size_t)row * KNN + k] = wi;
            if (cii == wi) {
                #pragma unroll
                for (int q = KNN - 1; q > 0; q--) { arr[q] = arr[q - 1]; ai[q] = ai[q - 1]; }
                arr[0] = -FLT_MAX; ai[0] = 0x7FFFFFFF;
            }
        }
    }
}

// ---------------- Y = W2 X, Z = (W1-W2) X (fp32) ---------------------------
__global__ void k_yz(const float* __restrict__ feat, const float* __restrict__ W,
                     int C, int Cout, int bstr) {
    __shared__ float As[16][64];
    __shared__ float B1[16][64];
    __shared__ float B2[16][64];
    int b = blockIdx.z;
    int n0 = blockIdx.x * 64, o0 = blockIdx.y * 64;
    const float* fb = feat + (size_t)b * bstr;
    int tx = threadIdx.x & 15, ty = threadIdx.x >> 4;
    float aU[4][4] = {}, aY[4][4] = {};
    for (int c0 = 0; c0 < C; c0 += 16) {
        for (int e = threadIdx.x; e < 1024; e += 256) {
            int kk = e >> 6, nn = e & 63;
            int c = c0 + kk;
            As[kk][nn] = (c < C) ? fb[(size_t)c * NPTS + n0 + nn] : 0.f;
        }
        for (int e = threadIdx.x; e < 1024; e += 256) {
            int kk = e & 15, oo = e >> 4;
            int c = c0 + kk;
            float w1 = 0.f, w2 = 0.f;
            if (c < C) {
                const float* wr = W + (size_t)(o0 + oo) * (2 * C);
                w1 = wr[c]; w2 = wr[C + c];
            }
            B1[kk][oo] = w1; B2[kk][oo] = w2;
        }
        __syncthreads();
        #pragma unroll
        for (int kk = 0; kk < 16; kk++) {
            float4 a4 = *(const float4*)&As[kk][ty * 4];
            float4 b14 = *(const float4*)&B1[kk][tx * 4];
            float4 b24 = *(const float4*)&B2[kk][tx * 4];
            float av[4] = {a4.x, a4.y, a4.z, a4.w};
            float b1v[4] = {b14.x, b14.y, b14.z, b14.w};
            float b2v[4] = {b24.x, b24.y, b24.z, b24.w};
            #pragma unroll
            for (int r = 0; r < 4; r++)
                #pragma unroll
                for (int s = 0; s < 4; s++) {
                    aU[r][s] = fmaf(av[r], b1v[s], aU[r][s]);
                    aY[r][s] = fmaf(av[r], b2v[s], aY[r][s]);
                }
        }
        __syncthreads();
    }
    #pragma unroll
    for (int r = 0; r < 4; r++) {
        int n = n0 + ty * 4 + r;
        size_t base = ((size_t)b * NPTS + n) * 256 + o0 + tx * 4;
        float4 y, z;
        y.x = aY[r][0]; y.y = aY[r][1]; y.z = aY[r][2]; y.w = aY[r][3];
        z.x = aU[r][0] - y.x; z.y = aU[r][1] - y.y;
        z.z = aU[r][2] - y.z; z.w = aU[r][3] - y.w;
        *(float4*)&g_Y[base] = y;
        *(float4*)&g_Z[base] = z;
    }
}

// ---------------- gather-max + BN + lrelu -> xcat + bf16 mirrors -----------
__global__ void k_gather(float* __restrict__ out, const float* __restrict__ gam,
                         const float* __restrict__ bet, int Cout, int co) {
    __shared__ int   sidx[32 * KNN];
    __shared__ float sout[256 * 33];
    int b = blockIdx.y, n0 = blockIdx.x * 32;
    for (int e = threadIdx.x; e < 32 * KNN; e += blockDim.x)
        sidx[e] = g_knn[((size_t)b * NPTS + n0) * KNN + e];
    __syncthreads();
    int o = threadIdx.x;
    float sc = gam[o] * BN_RSQ, bi = bet[o];
    const float* Yb = g_Y + (size_t)b * NPTS * 256;
    const float* Zb = g_Z + (size_t)b * NPTS * 256;
    for (int nn = 0; nn < 32; nn++) {
        float m = -FLT_MAX;
        #pragma unroll
        for (int k = 0; k < KNN; k++) {
            int j = sidx[nn * KNN + k];
            m = fmaxf(m, Yb[(size_t)j * 256 + o]);
        }
        float v = Zb[(size_t)(n0 + nn) * 256 + o] + m;
        v = lrelu(fmaf(v, sc, bi));
        sout[o * 33 + nn] = v;
    }
    __syncthreads();
    float* ob = out + (size_t)b * CAT_BSTR;
    for (int e = threadIdx.x; e < Cout * 32; e += blockDim.x) {
        int oo = e >> 5, nn = e & 31;
        float v = sout[oo * 33 + nn];
        ob[(size_t)oo * NPTS + n0 + nn] = v;
        uint16_t h, l;
        split_bf16(v, h, l);
        size_t bidx = ((size_t)b * 512 + co + oo) * NPTS + n0 + nn;
        g_ch[bidx] = h;
        g_cl[bidx] = l;
    }
}

// ---------------- global max + mean pool -> g_f (B, 2048) ------------------
__global__ void k_pool() {
    int b = blockIdx.y;
    int o = blockIdx.x * 256 + threadIdx.x;
    const float* h = g_h5 + (size_t)b * NPTS * 1024;
    float mx = -FLT_MAX, sm = 0.f;
    #pragma unroll 8
    for (int n = 0; n < NPTS; n++) {
        float v = h[(size_t)n * 1024 + o];
        mx = fmaxf(mx, v);
        sm += v;
    }
    g_f[b * 2048 + o] = mx;
    g_f[b * 2048 + 1024 + o] = sm * (1.0f / NPTS);
}

// ---------------- fc1: 2048->512, BN + lrelu -------------------------------
__global__ void k_fc1(const float* __restrict__ fw, const float* __restrict__ fb,
                      const float* __restrict__ gam, const float* __restrict__ bet) {
    int b = blockIdx.y;
    int w = threadIdx.x >> 5, lane = threadIdx.x & 31;
    int o = blockIdx.x * 8 + w;
    const float* f = g_f + b * 2048;
    const float* wr = fw + (size_t)o * 2048;
    float acc = 0.f;
    for (int c = lane; c < 2048; c += 32) acc = fmaf(f[c], wr[c], acc);
    #pragma unroll
    for (int s = 16; s > 0; s >>= 1) acc += __shfl_xor_sync(0xffffffffu, acc, s);
    if (lane == 0) {
        float v = acc + fb[o];
        v = lrelu(fmaf(v, gam[o] * BN_RSQ, bet[o]));
        g_fc1[b * 512 + o] = v;
    }
}

// ---------------- fc2: 512->256, BN (no lrelu) -> d_out --------------------
__global__ void k_fc2(const float* __restrict__ fw, const float* __restrict__ fb,
                      const float* __restrict__ gam, const float* __restrict__ bet,
                      float* __restrict__ out) {
    int b = blockIdx.y;
    int w = threadIdx.x >> 5, lane = threadIdx.x & 31;
    int o = blockIdx.x * 8 + w;
    const float* f = g_fc1 + b * 512;
    const float* wr = fw + (size_t)o * 512;
    float acc = 0.f;
    for (int c = lane; c < 512; c += 32) acc = fmaf(f[c], wr[c], acc);
    #pragma unroll
    for (int s = 16; s > 0; s >>= 1) acc += __shfl_xor_sync(0xffffffffu, acc, s);
    if (lane == 0) {
        float v = acc + fb[o];
        out[b * 256 + o] = fmaf(v, gam[o] * BN_RSQ, bet[o]);
    }
}

// ---------------- driver ---------------------------------------------------
static void run_edge(const float* feat, int C, int bstr,
                     const uint16_t* dh, const uint16_t* dl, int Ceff, int bfstr,
                     const float* W, const float* gam, const float* bet,
                     float* out, int Cout, int co) {
    k_xx<<<(BATCH * NPTS + 255) / 256, 256>>>(feat, C, bstr);
    k_dist_mma<<<dim3(NPTS / 128, NPTS / 128, BATCH), 256>>>(dh, dl, Ceff, bfstr);
    k_topk_compact<<<BATCH * NPTS / 8, 256>>>();
    k_topk_select<<<BATCH * NPTS / 8, 256>>>();
    k_yz<<<dim3(NPTS / 64, Cout / 64, BATCH), 256>>>(feat, W, C, Cout, bstr);
    k_gather<<<dim3(NPTS / 32, BATCH), Cout>>>(out, gam, bet, Cout, co);
}

extern "C" void kernel_launch(void* const* d_in, const int* in_sizes, int n_in,
                              void* d_out, int out_size) {
    const float* pts = (const float*)d_in[0];
    const float* w1 = (const float*)d_in[1];
    const float* g1 = (const float*)d_in[2];
    const float* b1 = (const float*)d_in[3];
    const float* w2 = (const float*)d_in[4];
    const float* g2 = (const float*)d_in[5];
    const float* b2 = (const float*)d_in[6];
    const float* w3 = (const float*)d_in[7];
    const float* g3 = (const float*)d_in[8];
    const float* b3 = (const float*)d_in[9];
    const float* w4 = (const float*)d_in[10];
    const float* g4 = (const float*)d_in[11];
    const float* b4 = (const float*)d_in[12];
    const float* w5 = (const float*)d_in[13];
    const float* g5 = (const float*)d_in[14];
    const float* b5 = (const float*)d_in[15];
    const float* fw1 = (const float*)d_in[16];
    const float* fb1 = (const float*)d_in[17];
    const float* g6 = (const float*)d_in[18];
    const float* b6 = (const float*)d_in[19];
    const float* fw2 = (const float*)d_in[20];
    const float* fb2 = (const float*)d_in[21];
    const float* g7 = (const float*)d_in[22];
    const float* b7 = (const float*)d_in[23];

    float *x0, *xcat;
    uint16_t *x0h, *x0l, *ch, *cl;
    cudaGetSymbolAddress((void**)&x0, g_x0);
    cudaGetSymbolAddress((void**)&xcat, g_xcat);
    cudaGetSymbolAddress((void**)&x0h, g_x0h);
    cudaGetSymbolAddress((void**)&x0l, g_x0l);
    cudaGetSymbolAddress((void**)&ch, g_ch);
    cudaGetSymbolAddress((void**)&cl, g_cl);
    float* x1 = xcat;                  // ch 0..63
    float* x2 = xcat + 64 * NPTS;      // ch 64..127
    float* x3 = xcat + 128 * NPTS;     // ch 128..255
    float* x4 = xcat + 256 * NPTS;     // ch 256..511

    k_transpose<<<(BATCH * NPTS + 255) / 256, 256>>>(pts);
    run_edge(x0, 3,   3 * NPTS, x0h, x0l, 16, 16 * NPTS,
             w1, g1, b1, x1, 64, 0);
    run_edge(x1, 64,  CAT_BSTR, ch,            cl,            64,  CAT_BSTR,
             w2, g2, b2, x2, 64, 64);
    run_edge(x2, 64,  CAT_BSTR, ch + 64 * NPTS,  cl + 64 * NPTS,  64,  CAT_BSTR,
             w3, g3, b3, x3, 128, 128);
    run_edge(x3, 128, CAT_BSTR, ch + 128 * NPTS, cl + 128 * NPTS, 128, CAT_BSTR,
             w4, g4, b4, x4, 256, 256);
    k_cvt_w5<<<(1024 * 512 + 255) / 256, 256>>>(w5);
    k_conv5_mma<<<dim3(NPTS / 128, 1024 / 128, BATCH), 256>>>(g5, b5);
    k_pool<<<dim3(1024 / 256, BATCH), 256>>>();
    k_fc1<<<dim3(512 / 8, BATCH), 256>>>(fw1, fb1, g6, b6);
    k_fc2<<<dim3(256 / 8, BATCH), 256>>>(fw2, fb2, g7, b7, (float*)d_out);
}

// round 9
// speedup vs baseline: 2.4573x; 1.2094x over previous
#include <cuda_runtime.h>
#include <cuda_bf16.h>
#include <cfloat>
#include <cstdint>
#include <cstddef>

#define NPTS 2048
#define BATCH 4
#define KNN 20
#define CAP 256

// ---------------- scratch (device globals; no allocation allowed) ----------
__device__ float g_x0[BATCH * 3 * NPTS];
__device__ float g_xcat[(size_t)BATCH * 512 * NPTS];     // fp32 concat feats
__device__ uint16_t g_x0h[BATCH * 16 * NPTS];            // bf16 hi of x0, Cpad=16
__device__ uint16_t g_x0l[BATCH * 16 * NPTS];            // bf16 lo
__device__ uint16_t g_ch[(size_t)BATCH * 512 * NPTS];    // bf16 hi of xcat
__device__ uint16_t g_cl[(size_t)BATCH * 512 * NPTS];    // bf16 lo
__device__ uint16_t g_w5h[1024 * 512];
__device__ uint16_t g_w5l[1024 * 512];
__device__ float g_xx[BATCH * NPTS];
__device__ float g_D[(size_t)BATCH * NPTS * NPTS];       // 64 MB
__device__ int   g_knn[BATCH * NPTS * KNN];
__device__ float g_cv[(size_t)BATCH * NPTS * CAP];
__device__ int   g_ci[(size_t)BATCH * NPTS * CAP];
__device__ int   g_cnt[BATCH * NPTS];
__device__ float g_Y[BATCH * NPTS * 256];
__device__ float g_Z[BATCH * NPTS * 256];
__device__ float g_h5[(size_t)BATCH * NPTS * 1024];
__device__ float g_f[BATCH * 2048];
__device__ float g_fc1[BATCH * 512];

__device__ __forceinline__ float lrelu(float v) { return v > 0.f ? v : 0.2f * v; }
#define BN_RSQ 0.99999500003749968750f
#define CAT_BSTR (512 * NPTS)
#define LDA 136   /* [k][m] tile row stride (halves): 8-row LDSM hits distinct banks */
#define LDB 24    /* conv5 W tile [o][k] row stride (halves) */

__device__ __forceinline__ void split_bf16(float x, uint16_t& h, uint16_t& l) {
    __nv_bfloat16 bh = __float2bfloat16(x);
    float r = x - __bfloat162float(bh);
    __nv_bfloat16 bl = __float2bfloat16(r);
    h = *reinterpret_cast<uint16_t*>(&bh);
    l = *reinterpret_cast<uint16_t*>(&bl);
}

__device__ __forceinline__ void mma_bf16(float c[4], const uint32_t a[4],
                                         uint32_t b0, uint32_t b1) {
    asm volatile(
        "mma.sync.aligned.m16n8k16.row.col.f32.bf16.bf16.f32 "
        "{%0,%1,%2,%3}, {%4,%5,%6,%7}, {%8,%9}, {%0,%1,%2,%3};"
        : "+f"(c[0]), "+f"(c[1]), "+f"(c[2]), "+f"(c[3])
        : "r"(a[0]), "r"(a[1]), "r"(a[2]), "r"(a[3]), "r"(b0), "r"(b1));
}

__device__ __forceinline__ uint32_t sptr(const void* p) {
    return (uint32_t)__cvta_generic_to_shared(p);
}
__device__ __forceinline__ void ldsm4t(uint32_t& r0, uint32_t& r1,
                                       uint32_t& r2, uint32_t& r3, uint32_t a) {
    asm volatile("ldmatrix.sync.aligned.m8n8.x4.trans.shared.b16 {%0,%1,%2,%3}, [%4];"
                 : "=r"(r0), "=r"(r1), "=r"(r2), "=r"(r3) : "r"(a));
}
__device__ __forceinline__ void ldsm4(uint32_t& r0, uint32_t& r1,
                                      uint32_t& r2, uint32_t& r3, uint32_t a) {
    asm volatile("ldmatrix.sync.aligned.m8n8.x4.shared.b16 {%0,%1,%2,%3}, [%4];"
                 : "=r"(r0), "=r"(r1), "=r"(r2), "=r"(r3) : "r"(a));
}

// ---------------- transpose points + bf16 split (Cpad=16) ------------------
__global__ void k_transpose(const float* __restrict__ pts) {
    int i = blockIdx.x * blockDim.x + threadIdx.x;
    if (i < BATCH * NPTS) {
        int b = i / NPTS, n = i % NPTS;
        #pragma unroll
        for (int c = 0; c < 3; c++) {
            float v = pts[(b * NPTS + n) * 3 + c];
            g_x0[(b * 3 + c) * NPTS + n] = v;
            uint16_t h, l;
            split_bf16(v, h, l);
            g_x0h[(b * 16 + c) * NPTS + n] = h;
            g_x0l[(b * 16 + c) * NPTS + n] = l;
        }
        #pragma unroll
        for (int c = 3; c < 16; c++) {
            g_x0h[(b * 16 + c) * NPTS + n] = 0;
            g_x0l[(b * 16 + c) * NPTS + n] = 0;
        }
    }
}

// ---------------- row norms (fp32 exact) -----------------------------------
__global__ void k_xx(const float* __restrict__ feat, int C, int bstr) {
    int i = blockIdx.x * blockDim.x + threadIdx.x;
    if (i < BATCH * NPTS) {
        int b = i / NPTS, n = i % NPTS;
        const float* f = feat + (size_t)b * bstr + n;
        float s = 0.f;
        for (int c = 0; c < C; c++) { float v = f[(size_t)c * NPTS]; s = fmaf(v, v, s); }
        g_xx[i] = s;
    }
}

// ---------------- w5 bf16 split --------------------------------------------
__global__ void k_cvt_w5(const float* __restrict__ w5) {
    int i = blockIdx.x * blockDim.x + threadIdx.x;
    if (i < 1024 * 512) {
        uint16_t h, l;
        split_bf16(w5[i], h, l);
        g_w5h[i] = h; g_w5l[i] = l;
    }
}

// ---------------- distance GEMM via split-bf16 mma + ldmatrix --------------
// grid (N/128, N/128, B), 256 thr, CTA 128x128, warp 32(m)x64(n), k-chunk 16.
// Tiles k-major ([k][m], [k][n]) = straight uint4 copies from (C,N) gmem.
__global__ __launch_bounds__(256, 2) void k_dist_mma(
        const uint16_t* __restrict__ srch, const uint16_t* __restrict__ srcl,
        int Ceff, int bstr) {
    __shared__ uint16_t Ah[16 * LDA], Al[16 * LDA];
    __shared__ uint16_t Bh[16 * LDA], Bl[16 * LDA];
    int b = blockIdx.z;
    int i0 = blockIdx.y * 128, j0 = blockIdx.x * 128;
    const uint16_t* ph = srch + (size_t)b * bstr;
    const uint16_t* pl = srcl + (size_t)b * bstr;
    int tid = threadIdx.x, lane = tid & 31, warp = tid >> 5;
    int wm = warp & 3, wn = warp >> 2;
    int sub = lane >> 3, Lr = lane & 7;
    float acc[2][8][4];
    #pragma unroll
    for (int mt = 0; mt < 2; mt++)
        #pragma unroll
        for (int nt = 0; nt < 8; nt++)
            #pragma unroll
            for (int q = 0; q < 4; q++) acc[mt][nt][q] = 0.f;

    for (int c0 = 0; c0 < Ceff; c0 += 16) {
        #pragma unroll
        for (int m = 0; m < 4; m++) {
            int idx = m * 256 + tid;
            int mat = idx >> 8, r = (idx >> 4) & 15, q = idx & 15;
            const uint16_t* src = (mat & 1) ? pl : ph;
            int base = (mat & 2) ? j0 : i0;
            uint16_t* dst = (mat == 0) ? Ah : (mat == 1) ? Al : (mat == 2) ? Bh : Bl;
            *(uint4*)&dst[r * LDA + q * 8] =
                *(const uint4*)&src[(size_t)(c0 + r) * NPTS + base + q * 8];
        }
        __syncthreads();
        #pragma unroll
        for (int pass = 0; pass < 3; pass++) {
            const uint16_t* A = (pass == 1) ? Al : Ah;
            const uint16_t* B = (pass == 2) ? Bl : Bh;
            // A fragments: [k][m] tile, x4.trans
            // sub0:(k=Lr,m+0)->a0  sub1:(k=Lr,m+8)->a1  sub2:(k8+Lr,m+0)->a2  sub3:(k8+Lr,m+8)->a3
            uint32_t af[2][4];
            #pragma unroll
            for (int mt = 0; mt < 2; mt++) {
                int krow = ((sub & 2) ? 8 : 0) + Lr;
                int mcol = wm * 32 + mt * 16 + ((sub & 1) ? 8 : 0);
                ldsm4t(af[mt][0], af[mt][1], af[mt][2], af[mt][3],
                       sptr(A + krow * LDA + mcol));
            }
            // B fragments: [k][n] tile, x4.trans
            // sub0:(k=Lr,n+0)->b0(n0)  sub1:(k8+Lr,n+0)->b1(n0)
            // sub2:(k=Lr,n+8)->b0(n8)  sub3:(k8+Lr,n+8)->b1(n8)
            uint32_t bf[8][2];
            #pragma unroll
            for (int u = 0; u < 4; u++) {
                int krow = ((sub & 1) ? 8 : 0) + Lr;
                int ncol = wn * 64 + u * 16 + ((sub & 2) ? 8 : 0);
                uint32_t r0, r1, r2, r3;
                ldsm4t(r0, r1, r2, r3, sptr(B + krow * LDA + ncol));
                bf[2 * u][0] = r0; bf[2 * u][1] = r1;
                bf[2 * u + 1][0] = r2; bf[2 * u + 1][1] = r3;
            }
            #pragma unroll
            for (int nt = 0; nt < 8; nt++) {
                mma_bf16(acc[0][nt], af[0], bf[nt][0], bf[nt][1]);
                mma_bf16(acc[1][nt], af[1], bf[nt][0], bf[nt][1]);
            }
        }
        __syncthreads();
    }
    // epilogue: 2*acc - xi - xj -> g_D   (c0,c1 = row g; c2,c3 = row g+8)
    int g = lane >> 2, t = lane & 3;
    #pragma unroll
    for (int mt = 0; mt < 2; mt++) {
        int r0 = i0 + wm * 32 + mt * 16 + g;
        int r1 = r0 + 8;
        float xi0 = g_xx[b * NPTS + r0];
        float xi1 = g_xx[b * NPTS + r1];
        #pragma unroll
        for (int nt = 0; nt < 8; nt++) {
            int j = j0 + wn * 64 + nt * 8 + 2 * t;
            float xj0 = g_xx[b * NPTS + j];
            float xj1 = g_xx[b * NPTS + j + 1];
            float2 v0, v1;
            v0.x = 2.f * acc[mt][nt][0] - xi0 - xj0;
            v0.y = 2.f * acc[mt][nt][1] - xi0 - xj1;
            v1.x = 2.f * acc[mt][nt][2] - xi1 - xj0;
            v1.y = 2.f * acc[mt][nt][3] - xi1 - xj1;
            *(float2*)&g_D[((size_t)b * NPTS + r0) * NPTS + j] = v0;
            *(float2*)&g_D[((size_t)b * NPTS + r1) * NPTS + j] = v1;
        }
    }
}

// ---------------- conv5 via split-bf16 mma + ldmatrix + BN + lrelu ---------
// grid (N/128, 1024/128, B). A = xcat [c][n] (trans), B = W5 [o][c] (non-trans).
__global__ __launch_bounds__(256, 2) void k_conv5_mma(
        const float* __restrict__ gam, const float* __restrict__ bet) {
    __shared__ uint16_t Ah[16 * LDA], Al[16 * LDA];
    __shared__ uint16_t Bh[128 * LDB], Bl[128 * LDB];
    int b = blockIdx.z;
    int n0 = blockIdx.x * 128, o0 = blockIdx.y * 128;
    const uint16_t* ph = g_ch + (size_t)b * CAT_BSTR;
    const uint16_t* pl = g_cl + (size_t)b * CAT_BSTR;
    int tid = threadIdx.x, lane = tid & 31, warp = tid >> 5;
    int wm = warp & 3, wn = warp >> 2;
    int sub = lane >> 3, Lr = lane & 7;
    float acc[2][8][4];
    #pragma unroll
    for (int mt = 0; mt < 2; mt++)
        #pragma unroll
        for (int nt = 0; nt < 8; nt++)
            #pragma unroll
            for (int q = 0; q < 4; q++) acc[mt][nt][q] = 0.f;

    for (int c0 = 0; c0 < 512; c0 += 16) {
        #pragma unroll
        for (int m = 0; m < 4; m++) {
            int idx = m * 256 + tid;
            if (idx < 512) {                          // A tiles: [k][n] rows
                int mat = idx >> 8, r = (idx >> 4) & 15, q = idx & 15;
                const uint16_t* src = mat ? pl : ph;
                uint16_t* dst = mat ? Al : Ah;
                *(uint4*)&dst[r * LDA + q * 8] =
                    *(const uint4*)&src[(size_t)(c0 + r) * NPTS + n0 + q * 8];
            } else {                                  // B tiles: [o][k] rows
                int j = idx - 512;
                int mat = j >> 8, row = (j >> 1) & 127, q = j & 1;
                const uint16_t* src = mat ? g_w5l : g_w5h;
                uint16_t* dst = mat ? Bl : Bh;
                *(uint4*)&dst[row * LDB + q * 8] =
                    *(const uint4*)&src[(size_t)(o0 + row) * 512 + c0 + q * 8];
            }
        }
        __syncthreads();
        #pragma unroll
        for (int pass = 0; pass < 3; pass++) {
            const uint16_t* A = (pass == 1) ? Al : Ah;
            const uint16_t* B = (pass == 2) ? Bl : Bh;
            uint32_t af[2][4];
            #pragma unroll
            for (int mt = 0; mt < 2; mt++) {
                int krow = ((sub & 2) ? 8 : 0) + Lr;
                int mcol = wm * 32 + mt * 16 + ((sub & 1) ? 8 : 0);
                ldsm4t(af[mt][0], af[mt][1], af[mt][2], af[mt][3],
                       sptr(A + krow * LDA + mcol));
            }
            // B [o][k] non-trans: sub0:(o+Lr,k0)->b0(n0) sub1:(o+Lr,k8)->b1(n0)
            //                     sub2:(o+8+Lr,k0)->b0(n8) sub3:(o+8+Lr,k8)->b1(n8)
            uint32_t bf[8][2];
            #pragma unroll
            for (int u = 0; u < 4; u++) {
                int orow = wn * 64 + u * 16 + ((sub & 2) ? 8 : 0) + Lr;
                int kcol = (sub & 1) ? 8 : 0;
                uint32_t r0, r1, r2, r3;
                ldsm4(r0, r1, r2, r3, sptr(B + orow * LDB + kcol));
                bf[2 * u][0] = r0; bf[2 * u][1] = r1;
                bf[2 * u + 1][0] = r2; bf[2 * u + 1][1] = r3;
            }
            #pragma unroll
            for (int nt = 0; nt < 8; nt++) {
                mma_bf16(acc[0][nt], af[0], bf[nt][0], bf[nt][1]);
                mma_bf16(acc[1][nt], af[1], bf[nt][0], bf[nt][1]);
            }
        }
        __syncthreads();
    }
    // epilogue: BN + lrelu -> g_h5 (n-major)
    int g = lane >> 2, t = lane & 3;
    #pragma unroll
    for (int mt = 0; mt < 2; mt++) {
        int r0 = n0 + wm * 32 + mt * 16 + g;
        int r1 = r0 + 8;
        #pragma unroll
        for (int nt = 0; nt < 8; nt++) {
            int o = o0 + wn * 64 + nt * 8 + 2 * t;
            float sc0 = gam[o] * BN_RSQ, bi0 = bet[o];
            float sc1 = gam[o + 1] * BN_RSQ, bi1 = bet[o + 1];
            float2 v0, v1;
            v0.x = lrelu(fmaf(acc[mt][nt][0], sc0, bi0));
            v0.y = lrelu(fmaf(acc[mt][nt][1], sc1, bi1));
            v1.x = lrelu(fmaf(acc[mt][nt][2], sc0, bi0));
            v1.y = lrelu(fmaf(acc[mt][nt][3], sc1, bi1));
            *(float2*)&g_h5[((size_t)b * NPTS + r0) * 1024 + o] = v0;
            *(float2*)&g_h5[((size_t)b * NPTS + r1) * 1024 + o] = v1;
        }
    }
}

// ---------------- top-K stage 1: threshold + compact -----------------------
__global__ void k_topk_compact() {
    const unsigned FULL = 0xffffffffu;
    int lane = threadIdx.x & 31, warp = threadIdx.x >> 5;
    int row = blockIdx.x * 8 + warp;
    const float* drow = g_D + (size_t)row * NPTS;

    float v1 = -FLT_MAX;
    #pragma unroll
    for (int t = 0; t < NPTS / 128; t++) {
        float4 q = *(const float4*)&drow[t * 128 + lane * 4];
        v1 = fmaxf(v1, fmaxf(fmaxf(q.x, q.y), fmaxf(q.z, q.w)));
    }
    float v = v1;
    #pragma unroll
    for (int k = 2; k <= 32; k <<= 1) {
        #pragma unroll
        for (int j = k >> 1; j > 0; j >>= 1) {
            float o = __shfl_xor_sync(FULL, v, j);
            bool takeMax = (((lane & k) == 0) == ((lane & j) == 0));
            v = takeMax ? fmaxf(v, o) : fminf(v, o);
        }
    }
    float Te = __shfl_sync(FULL, v, KNN - 1);

    float* cv = g_cv + (size_t)row * CAP;
    int*   ci = g_ci + (size_t)row * CAP;
    unsigned lmask = (1u << lane) - 1u;
    unsigned cnt = 0;
    #pragma unroll 2
    for (int t = 0; t < NPTS / 128; t++) {
        int jb = t * 128 + lane * 4;
        float4 q = *(const float4*)&drow[jb];
        float vals[4] = {q.x, q.y, q.z, q.w};
        #pragma unroll
        for (int m = 0; m < 4; m++) {
            bool pass = vals[m] >= Te;
            unsigned mk = __ballot_sync(FULL, pass);
            if (pass) {
                unsigned pos = cnt + __popc(mk & lmask);
                if (pos < CAP) { cv[pos] = vals[m]; ci[pos] = jb + m; }
            }
            cnt += __popc(mk);
        }
    }
    if (lane == 0) g_cnt[row] = (int)cnt;
}

// ---------------- top-K stage 2: exact select ------------------------------
__global__ void k_topk_select() {
    const unsigned FULL = 0xffffffffu;
    int lane = threadIdx.x & 31, warp = threadIdx.x >> 5;
    int row = blockIdx.x * 8 + warp;
    int cnt = g_cnt[row];

    if (cnt <= CAP) {
        const float* cv = g_cv + (size_t)row * CAP;
        const int*   ci = g_ci + (size_t)row * CAP;
        float lv[8]; int li[8];
        #pragma unroll
        for (int q = 0; q < 8; q++) {
            int p = q * 32 + lane;
            bool in = p < cnt;
            lv[q] = in ? __ldg(&cv[p]) : -FLT_MAX;
            li[q] = in ? __ldg(&ci[p]) : 0x7FFFFFFF;
        }
        #pragma unroll 1
        for (int k = 0; k < KNN; k++) {
            float bv = -FLT_MAX; int bi = 0x7FFFFFFF, bq = 0;
            #pragma unroll
            for (int q = 0; q < 8; q++) {
                if (lv[q] > bv || (lv[q] == bv && li[q] < bi)) {
                    bv = lv[q]; bi = li[q]; bq = q;
                }
            }
            float wv = bv; int wi = bi;
            #pragma unroll
            for (int s = 16; s > 0; s >>= 1) {
                float ov = __shfl_xor_sync(FULL, wv, s);
                int   oi = __shfl_xor_sync(FULL, wi, s);
                if (ov > wv || (ov == wv && oi < wi)) { wv = ov; wi = oi; }
            }
            if (lane == 0) g_knn[(size_t)row * KNN + k] = wi;
            if (bv == wv && bi == wi) { lv[bq] = -FLT_MAX; li[bq] = 0x7FFFFFFF; }
        }
    } else {
        const float* drow = g_D + (size_t)row * NPTS;
        float arr[KNN]; int ai[KNN];
        #pragma unroll
        for (int q = 0; q < KNN; q++) { arr[q] = -FLT_MAX; ai[q] = 0x7FFFFFFF; }
        #pragma unroll 1
        for (int t = 0; t < NPTS / 128; t++) {
            int jb = t * 128 + lane * 4;
            float4 v4 = *(const float4*)&drow[jb];
            float vv[4] = {v4.x, v4.y, v4.z, v4.w};
            #pragma unroll
            for (int m = 0; m < 4; m++) {
                float vx = vv[m];
                if (vx > arr[0]) {
                    arr[0] = vx; ai[0] = jb + m;
                    #pragma unroll
                    for (int q = 0; q < KNN - 1; q++) {
                        if (arr[q + 1] < arr[q]) {
                            float tv = arr[q]; arr[q] = arr[q + 1]; arr[q + 1] = tv;
                            int ti = ai[q]; ai[q] = ai[q + 1]; ai[q + 1] = ti;
                        }
                    }
                }
            }
        }
        #pragma unroll 1
        for (int k = 0; k < KNN; k++) {
            float cvv = arr[KNN - 1]; int cii = ai[KNN - 1];
            float wv = cvv; int wi = cii;
            #pragma unroll
            for (int s = 16; s > 0; s >>= 1) {
                float ov = __shfl_xor_sync(FULL, wv, s);
                int   oi = __shfl_xor_sync(FULL, wi, s);
                if (ov > wv || (ov == wv && oi < wi)) { wv = ov; wi = oi; }
            }
            if (lane == 0) g_knn[(size_t)row * KNN + k] = wi;
            if (cii == wi) {
                #pragma unroll
                for (int q = KNN - 1; q > 0; q--) { arr[q] = arr[q - 1]; ai[q] = ai[q - 1]; }
                arr[0] = -FLT_MAX; ai[0] = 0x7FFFFFFF;
            }
        }
    }
}

// ---------------- Y = W2 X, Z = (W1-W2) X (fp32) ---------------------------
__global__ void k_yz(const float* __restrict__ feat, const float* __restrict__ W,
                     int C, int Cout, int bstr) {
    __shared__ float As[16][64];
    __shared__ float B1[16][64];
    __shared__ float B2[16][64];
    int b = blockIdx.z;
    int n0 = blockIdx.x * 64, o0 = blockIdx.y * 64;
    const float* fb = feat + (size_t)b * bstr;
    int tx = threadIdx.x & 15, ty = threadIdx.x >> 4;
    float aU[4][4] = {}, aY[4][4] = {};
    for (int c0 = 0; c0 < C; c0 += 16) {
        for (int e = threadIdx.x; e < 1024; e += 256) {
            int kk = e >> 6, nn = e & 63;
            int c = c0 + kk;
            As[kk][nn] = (c < C) ? fb[(size_t)c * NPTS + n0 + nn] : 0.f;
        }
        for (int e = threadIdx.x; e < 1024; e += 256) {
            int kk = e & 15, oo = e >> 4;
            int c = c0 + kk;
            float w1 = 0.f, w2 = 0.f;
            if (c < C) {
                const float* wr = W + (size_t)(o0 + oo) * (2 * C);
                w1 = wr[c]; w2 = wr[C + c];
            }
            B1[kk][oo] = w1; B2[kk][oo] = w2;
        }
        __syncthreads();
        #pragma unroll
        for (int kk = 0; kk < 16; kk++) {
            float4 a4 = *(const float4*)&As[kk][ty * 4];
            float4 b14 = *(const float4*)&B1[kk][tx * 4];
            float4 b24 = *(const float4*)&B2[kk][tx * 4];
            float av[4] = {a4.x, a4.y, a4.z, a4.w};
            float b1v[4] = {b14.x, b14.y, b14.z, b14.w};
            float b2v[4] = {b24.x, b24.y, b24.z, b24.w};
            #pragma unroll
            for (int r = 0; r < 4; r++)
                #pragma unroll
                for (int s = 0; s < 4; s++) {
                    aU[r][s] = fmaf(av[r], b1v[s], aU[r][s]);
                    aY[r][s] = fmaf(av[r], b2v[s], aY[r][s]);
                }
        }
        __syncthreads();
    }
    #pragma unroll
    for (int r = 0; r < 4; r++) {
        int n = n0 + ty * 4 + r;
        size_t base = ((size_t)b * NPTS + n) * 256 + o0 + tx * 4;
        float4 y, z;
        y.x = aY[r][0]; y.y = aY[r][1]; y.z = aY[r][2]; y.w = aY[r][3];
        z.x = aU[r][0] - y.x; z.y = aU[r][1] - y.y;
        z.z = aU[r][2] - y.z; z.w = aU[r][3] - y.w;
        *(float4*)&g_Y[base] = y;
        *(float4*)&g_Z[base] = z;
    }
}

// ---------------- gather-max + BN + lrelu -> xcat + bf16 mirrors -----------
__global__ void k_gather(float* __restrict__ out, const float* __restrict__ gam,
                         const float* __restrict__ bet, int Cout, int co) {
    __shared__ int   sidx[32 * KNN];
    __shared__ float sout[256 * 33];
    int b = blockIdx.y, n0 = blockIdx.x * 32;
    for (int e = threadIdx.x; e < 32 * KNN; e += blockDim.x)
        sidx[e] = g_knn[((size_t)b * NPTS + n0) * KNN + e];
    __syncthreads();
    int o = threadIdx.x;
    float sc = gam[o] * BN_RSQ, bi = bet[o];
    const float* Yb = g_Y + (size_t)b * NPTS * 256;
    const float* Zb = g_Z + (size_t)b * NPTS * 256;
    for (int nn = 0; nn < 32; nn++) {
        float m = -FLT_MAX;
        #pragma unroll
        for (int k = 0; k < KNN; k++) {
            int j = sidx[nn * KNN + k];
            m = fmaxf(m, Yb[(size_t)j * 256 + o]);
        }
        float v = Zb[(size_t)(n0 + nn) * 256 + o] + m;
        v = lrelu(fmaf(v, sc, bi));
        sout[o * 33 + nn] = v;
    }
    __syncthreads();
    float* ob = out + (size_t)b * CAT_BSTR;
    for (int e = threadIdx.x; e < Cout * 32; e += blockDim.x) {
        int oo = e >> 5, nn = e & 31;
        float v = sout[oo * 33 + nn];
        ob[(size_t)oo * NPTS + n0 + nn] = v;
        uint16_t h, l;
        split_bf16(v, h, l);
        size_t bidx = ((size_t)b * 512 + co + oo) * NPTS + n0 + nn;
        g_ch[bidx] = h;
        g_cl[bidx] = l;
    }
}

// ---------------- global max + mean pool -> g_f (B, 2048) ------------------
__global__ void k_pool() {
    int b = blockIdx.y;
    int o = blockIdx.x * 256 + threadIdx.x;
    const float* h = g_h5 + (size_t)b * NPTS * 1024;
    float mx = -FLT_MAX, sm = 0.f;
    #pragma unroll 8
    for (int n = 0; n < NPTS; n++) {
        float v = h[(size_t)n * 1024 + o];
        mx = fmaxf(mx, v);
        sm += v;
    }
    g_f[b * 2048 + o] = mx;
    g_f[b * 2048 + 1024 + o] = sm * (1.0f / NPTS);
}

// ---------------- fc1: 2048->512, BN + lrelu -------------------------------
__global__ void k_fc1(const float* __restrict__ fw, const float* __restrict__ fb,
                      const float* __restrict__ gam, const float* __restrict__ bet) {
    int b = blockIdx.y;
    int w = threadIdx.x >> 5, lane = threadIdx.x & 31;
    int o = blockIdx.x * 8 + w;
    const float* f = g_f + b * 2048;
    const float* wr = fw + (size_t)o * 2048;
    float acc = 0.f;
    for (int c = lane; c < 2048; c += 32) acc = fmaf(f[c], wr[c], acc);
    #pragma unroll
    for (int s = 16; s > 0; s >>= 1) acc += __shfl_xor_sync(0xffffffffu, acc, s);
    if (lane == 0) {
        float v = acc + fb[o];
        v = lrelu(fmaf(v, gam[o] * BN_RSQ, bet[o]));
        g_fc1[b * 512 + o] = v;
    }
}

// ---------------- fc2: 512->256, BN (no lrelu) -> d_out --------------------
__global__ void k_fc2(const float* __restrict__ fw, const float* __restrict__ fb,
                      const float* __restrict__ gam, const float* __restrict__ bet,
                      float* __restrict__ out) {
    int b = blockIdx.y;
    int w = threadIdx.x >> 5, lane = threadIdx.x & 31;
    int o = blockIdx.x * 8 + w;
    const float* f = g_fc1 + b * 512;
    const float* wr = fw + (size_t)o * 512;
    float acc = 0.f;
    for (int c = lane; c < 512; c += 32) acc = fmaf(f[c], wr[c], acc);
    #pragma unroll
    for (int s = 16; s > 0; s >>= 1) acc += __shfl_xor_sync(0xffffffffu, acc, s);
    if (lane == 0) {
        float v = acc + fb[o];
        out[b * 256 + o] = fmaf(v, gam[o] * BN_RSQ, bet[o]);
    }
}

// ---------------- driver ---------------------------------------------------
static void run_edge(const float* feat, int C, int bstr,
                     const uint16_t* dh, const uint16_t* dl, int Ceff, int bfstr,
                     const float* W, const float* gam, const float* bet,
                     float* out, int Cout, int co) {
    k_xx<<<(BATCH * NPTS + 255) / 256, 256>>>(feat, C, bstr);
    k_dist_mma<<<dim3(NPTS / 128, NPTS / 128, BATCH), 256>>>(dh, dl, Ceff, bfstr);
    k_topk_compact<<<BATCH * NPTS / 8, 256>>>();
    k_topk_select<<<BATCH * NPTS / 8, 256>>>();
    k_yz<<<dim3(NPTS / 64, Cout / 64, BATCH), 256>>>(feat, W, C, Cout, bstr);
    k_gather<<<dim3(NPTS / 32, BATCH), Cout>>>(out, gam, bet, Cout, co);
}

extern "C" void kernel_launch(void* const* d_in, const int* in_sizes, int n_in,
                              void* d_out, int out_size) {
    const float* pts = (const float*)d_in[0];
    const float* w1 = (const float*)d_in[1];
    const float* g1 = (const float*)d_in[2];
    const float* b1 = (const float*)d_in[3];
    const float* w2 = (const float*)d_in[4];
    const float* g2 = (const float*)d_in[5];
    const float* b2 = (const float*)d_in[6];
    const float* w3 = (const float*)d_in[7];
    const float* g3 = (const float*)d_in[8];
    const float* b3 = (const float*)d_in[9];
    const float* w4 = (const float*)d_in[10];
    const float* g4 = (const float*)d_in[11];
    const float* b4 = (const float*)d_in[12];
    const float* w5 = (const float*)d_in[13];
    const float* g5 = (const float*)d_in[14];
    const float* b5 = (const float*)d_in[15];
    const float* fw1 = (const float*)d_in[16];
    const float* fb1 = (const float*)d_in[17];
    const float* g6 = (const float*)d_in[18];
    const float* b6 = (const float*)d_in[19];
    const float* fw2 = (const float*)d_in[20];
    const float* fb2 = (const float*)d_in[21];
    const float* g7 = (const float*)d_in[22];
    const float* b7 = (const float*)d_in[23];

    float *x0, *xcat;
    uint16_t *x0h, *x0l, *ch, *cl;
    cudaGetSymbolAddress((void**)&x0, g_x0);
    cudaGetSymbolAddress((void**)&xcat, g_xcat);
    cudaGetSymbolAddress((void**)&x0h, g_x0h);
    cudaGetSymbolAddress((void**)&x0l, g_x0l);
    cudaGetSymbolAddress((void**)&ch, g_ch);
    cudaGetSymbolAddress((void**)&cl, g_cl);
    float* x1 = xcat;                  // ch 0..63
    float* x2 = xcat + 64 * NPTS;      // ch 64..127
    float* x3 = xcat + 128 * NPTS;     // ch 128..255
    float* x4 = xcat + 256 * NPTS;     // ch 256..511

    k_transpose<<<(BATCH * NPTS + 255) / 256, 256>>>(pts);
    run_edge(x0, 3,   3 * NPTS, x0h, x0l, 16, 16 * NPTS,
             w1, g1, b1, x1, 64, 0);
    run_edge(x1, 64,  CAT_BSTR, ch,              cl,              64,  CAT_BSTR,
             w2, g2, b2, x2, 64, 64);
    run_edge(x2, 64,  CAT_BSTR, ch + 64 * NPTS,  cl + 64 * NPTS,  64,  CAT_BSTR,
             w3, g3, b3, x3, 128, 128);
    run_edge(x3, 128, CAT_BSTR, ch + 128 * NPTS, cl + 128 * NPTS, 128, CAT_BSTR,
             w4, g4, b4, x4, 256, 256);
    k_cvt_w5<<<(1024 * 512 + 255) / 256, 256>>>(w5);
    k_conv5_mma<<<dim3(NPTS / 128, 1024 / 128, BATCH), 256>>>(g5, b5);
    k_pool<<<dim3(1024 / 256, BATCH), 256>>>();
    k_fc1<<<dim3(512 / 8, BATCH), 256>>>(fw1, fb1, g6, b6);
    k_fc2<<<dim3(256 / 8, BATCH), 256>>>(fw2, fb2, g7, b7, (float*)d_out);
}

// round 11
// speedup vs baseline: 2.7259x; 1.1093x over previous
#include <cuda_runtime.h>
#include <cuda_bf16.h>
#include <cfloat>
#include <cstdint>
#include <cstddef>

#define NPTS 2048
#define BATCH 4
#define KNN 20
#define CAP 256

// ---------------- scratch (device globals; no allocation allowed) ----------
__device__ float g_x0[BATCH * 3 * NPTS];
__device__ float g_xcat[(size_t)BATCH * 512 * NPTS];     // fp32 concat feats
__device__ uint16_t g_x0h[BATCH * 16 * NPTS];            // bf16 hi of x0, Cpad=16
__device__ uint16_t g_x0l[BATCH * 16 * NPTS];            // bf16 lo
__device__ uint16_t g_ch[(size_t)BATCH * 512 * NPTS];    // bf16 hi of xcat
__device__ uint16_t g_cl[(size_t)BATCH * 512 * NPTS];    // bf16 lo
__device__ uint16_t g_w5h[1024 * 512];
__device__ uint16_t g_w5l[1024 * 512];
__device__ float g_xx[BATCH * NPTS];
__device__ float g_D[(size_t)BATCH * NPTS * NPTS];       // 64 MB
__device__ float g_smax[(size_t)BATCH * NPTS * 32];      // per-row 64-col chunk maxes
__device__ int   g_knn[BATCH * NPTS * KNN];
__device__ float g_Y[BATCH * NPTS * 256];
__device__ float g_Z[BATCH * NPTS * 256];
__device__ float g_pmax[BATCH * 16 * 1024];              // conv5 partial max
__device__ float g_psum[BATCH * 16 * 1024];              // conv5 partial sum
__device__ float g_f[BATCH * 2048];
__device__ float g_fc1[BATCH * 512];

__device__ __forceinline__ float lrelu(float v) { return v > 0.f ? v : 0.2f * v; }
#define BN_RSQ 0.99999500003749968750f
#define CAT_BSTR (512 * NPTS)
#define LDA 136   /* [k][m] tile row stride (halves) */
#define LDB 24    /* conv5 W tile [o][k] row stride (halves) */

__device__ __forceinline__ void split_bf16(float x, uint16_t& h, uint16_t& l) {
    __nv_bfloat16 bh = __float2bfloat16(x);
    float r = x - __bfloat162float(bh);
    __nv_bfloat16 bl = __float2bfloat16(r);
    h = *reinterpret_cast<uint16_t*>(&bh);
    l = *reinterpret_cast<uint16_t*>(&bl);
}

__device__ __forceinline__ void mma_bf16(float c[4], const uint32_t a[4],
                                         uint32_t b0, uint32_t b1) {
    asm volatile(
        "mma.sync.aligned.m16n8k16.row.col.f32.bf16.bf16.f32 "
        "{%0,%1,%2,%3}, {%4,%5,%6,%7}, {%8,%9}, {%0,%1,%2,%3};"
        : "+f"(c[0]), "+f"(c[1]), "+f"(c[2]), "+f"(c[3])
        : "r"(a[0]), "r"(a[1]), "r"(a[2]), "r"(a[3]), "r"(b0), "r"(b1));
}

__device__ __forceinline__ uint32_t sptr(const void* p) {
    return (uint32_t)__cvta_generic_to_shared(p);
}
__device__ __forceinline__ void ldsm4t(uint32_t& r0, uint32_t& r1,
                                       uint32_t& r2, uint32_t& r3, uint32_t a) {
    asm volatile("ldmatrix.sync.aligned.m8n8.x4.trans.shared.b16 {%0,%1,%2,%3}, [%4];"
                 : "=r"(r0), "=r"(r1), "=r"(r2), "=r"(r3) : "r"(a));
}
__device__ __forceinline__ void ldsm4(uint32_t& r0, uint32_t& r1,
                                      uint32_t& r2, uint32_t& r3, uint32_t a) {
    asm volatile("ldmatrix.sync.aligned.m8n8.x4.shared.b16 {%0,%1,%2,%3}, [%4];"
                 : "=r"(r0), "=r"(r1), "=r"(r2), "=r"(r3) : "r"(a));
}

// ---------------- transpose points + bf16 split (Cpad=16) ------------------
__global__ void k_transpose(const float* __restrict__ pts) {
    int i = blockIdx.x * blockDim.x + threadIdx.x;
    if (i < BATCH * NPTS) {
        int b = i / NPTS, n = i % NPTS;
        #pragma unroll
        for (int c = 0; c < 3; c++) {
            float v = pts[(b * NPTS + n) * 3 + c];
            g_x0[(b * 3 + c) * NPTS + n] = v;
            uint16_t h, l;
            split_bf16(v, h, l);
            g_x0h[(b * 16 + c) * NPTS + n] = h;
            g_x0l[(b * 16 + c) * NPTS + n] = l;
        }
        #pragma unroll
        for (int c = 3; c < 16; c++) {
            g_x0h[(b * 16 + c) * NPTS + n] = 0;
            g_x0l[(b * 16 + c) * NPTS + n] = 0;
        }
    }
}

// ---------------- row norms (fp32 exact) -----------------------------------
__global__ void k_xx(const float* __restrict__ feat, int C, int bstr) {
    int i = blockIdx.x * blockDim.x + threadIdx.x;
    if (i < BATCH * NPTS) {
        int b = i / NPTS, n = i % NPTS;
        const float* f = feat + (size_t)b * bstr + n;
        float s = 0.f;
        for (int c = 0; c < C; c++) { float v = f[(size_t)c * NPTS]; s = fmaf(v, v, s); }
        g_xx[i] = s;
    }
}

// ---------------- w5 bf16 split --------------------------------------------
__global__ void k_cvt_w5(const float* __restrict__ w5) {
    int i = blockIdx.x * blockDim.x + threadIdx.x;
    if (i < 1024 * 512) {
        uint16_t h, l;
        split_bf16(w5[i], h, l);
        g_w5h[i] = h; g_w5l[i] = l;
    }
}

// ---------------- distance GEMM via split-bf16 mma + ldmatrix --------------
// Also emits per-row 64-col chunk maxes to g_smax (for single-pass topk).
__global__ __launch_bounds__(256, 2) void k_dist_mma(
        const uint16_t* __restrict__ srch, const uint16_t* __restrict__ srcl,
        int Ceff, int bstr) {
    __shared__ uint16_t Ah[16 * LDA], Al[16 * LDA];
    __shared__ uint16_t Bh[16 * LDA], Bl[16 * LDA];
    const unsigned FULL = 0xffffffffu;
    int b = blockIdx.z;
    int i0 = blockIdx.y * 128, j0 = blockIdx.x * 128;
    const uint16_t* ph = srch + (size_t)b * bstr;
    const uint16_t* pl = srcl + (size_t)b * bstr;
    int tid = threadIdx.x, lane = tid & 31, warp = tid >> 5;
    int wm = warp & 3, wn = warp >> 2;
    int sub = lane >> 3, Lr = lane & 7;
    float acc[2][8][4];
    #pragma unroll
    for (int mt = 0; mt < 2; mt++)
        #pragma unroll
        for (int nt = 0; nt < 8; nt++)
            #pragma unroll
            for (int q = 0; q < 4; q++) acc[mt][nt][q] = 0.f;

    for (int c0 = 0; c0 < Ceff; c0 += 16) {
        #pragma unroll
        for (int m = 0; m < 4; m++) {
            int idx = m * 256 + tid;
            int mat = idx >> 8, r = (idx >> 4) & 15, q = idx & 15;
            const uint16_t* src = (mat & 1) ? pl : ph;
            int base = (mat & 2) ? j0 : i0;
            uint16_t* dst = (mat == 0) ? Ah : (mat == 1) ? Al : (mat == 2) ? Bh : Bl;
            *(uint4*)&dst[r * LDA + q * 8] =
                *(const uint4*)&src[(size_t)(c0 + r) * NPTS + base + q * 8];
        }
        __syncthreads();
        #pragma unroll
        for (int pass = 0; pass < 3; pass++) {
            const uint16_t* A = (pass == 1) ? Al : Ah;
            const uint16_t* B = (pass == 2) ? Bl : Bh;
            uint32_t af[2][4];
            #pragma unroll
            for (int mt = 0; mt < 2; mt++) {
                int krow = ((sub & 2) ? 8 : 0) + Lr;
                int mcol = wm * 32 + mt * 16 + ((sub & 1) ? 8 : 0);
                ldsm4t(af[mt][0], af[mt][1], af[mt][2], af[mt][3],
                       sptr(A + krow * LDA + mcol));
            }
            uint32_t bf[8][2];
            #pragma unroll
            for (int u = 0; u < 4; u++) {
                int krow = ((sub & 1) ? 8 : 0) + Lr;
                int ncol = wn * 64 + u * 16 + ((sub & 2) ? 8 : 0);
                uint32_t r0, r1, r2, r3;
                ldsm4t(r0, r1, r2, r3, sptr(B + krow * LDA + ncol));
                bf[2 * u][0] = r0; bf[2 * u][1] = r1;
                bf[2 * u + 1][0] = r2; bf[2 * u + 1][1] = r3;
            }
            #pragma unroll
            for (int nt = 0; nt < 8; nt++) {
                mma_bf16(acc[0][nt], af[0], bf[nt][0], bf[nt][1]);
                mma_bf16(acc[1][nt], af[1], bf[nt][0], bf[nt][1]);
            }
        }
        __syncthreads();
    }
    // epilogue: 2*acc - xi - xj -> g_D, plus warp 64-col chunk max -> g_smax
    int g = lane >> 2, t = lane & 3;
    #pragma unroll
    for (int mt = 0; mt < 2; mt++) {
        int r0 = i0 + wm * 32 + mt * 16 + g;
        int r1 = r0 + 8;
        float xi0 = g_xx[b * NPTS + r0];
        float xi1 = g_xx[b * NPTS + r1];
        float m0 = -FLT_MAX, m1 = -FLT_MAX;
        #pragma unroll
        for (int nt = 0; nt < 8; nt++) {
            int j = j0 + wn * 64 + nt * 8 + 2 * t;
            float xj0 = g_xx[b * NPTS + j];
            float xj1 = g_xx[b * NPTS + j + 1];
            float2 v0, v1;
            v0.x = 2.f * acc[mt][nt][0] - xi0 - xj0;
            v0.y = 2.f * acc[mt][nt][1] - xi0 - xj1;
            v1.x = 2.f * acc[mt][nt][2] - xi1 - xj0;
            v1.y = 2.f * acc[mt][nt][3] - xi1 - xj1;
            m0 = fmaxf(m0, fmaxf(v0.x, v0.y));
            m1 = fmaxf(m1, fmaxf(v1.x, v1.y));
            *(float2*)&g_D[((size_t)b * NPTS + r0) * NPTS + j] = v0;
            *(float2*)&g_D[((size_t)b * NPTS + r1) * NPTS + j] = v1;
        }
        m0 = fmaxf(m0, __shfl_xor_sync(FULL, m0, 1));
        m0 = fmaxf(m0, __shfl_xor_sync(FULL, m0, 2));
        m1 = fmaxf(m1, __shfl_xor_sync(FULL, m1, 1));
        m1 = fmaxf(m1, __shfl_xor_sync(FULL, m1, 2));
        if (t == 0) {
            int ch = (j0 >> 6) + wn;
            g_smax[(size_t)(b * NPTS + r0) * 32 + ch] = m0;
            g_smax[(size_t)(b * NPTS + r1) * 32 + ch] = m1;
        }
    }
}

// ---------------- conv5 via split-bf16 mma + fused partial pooling ---------
// grid (16, 8, B). Epilogue reduces its 128 rows -> per-block (max,sum)/channel.
__global__ __launch_bounds__(256, 2) void k_conv5_mma(
        const float* __restrict__ gam, const float* __restrict__ bet) {
    __shared__ uint16_t Ah[16 * LDA], Al[16 * LDA];
    __shared__ uint16_t Bh[128 * LDB], Bl[128 * LDB];
    __shared__ float sm_max[8][64];
    __shared__ float sm_sum[8][64];
    const unsigned FULL = 0xffffffffu;
    int b = blockIdx.z;
    int n0 = blockIdx.x * 128, o0 = blockIdx.y * 128;
    const uint16_t* ph = g_ch + (size_t)b * CAT_BSTR;
    const uint16_t* pl = g_cl + (size_t)b * CAT_BSTR;
    int tid = threadIdx.x, lane = tid & 31, warp = tid >> 5;
    int wm = warp & 3, wn = warp >> 2;
    int sub = lane >> 3, Lr = lane & 7;
    float acc[2][8][4];
    #pragma unroll
    for (int mt = 0; mt < 2; mt++)
        #pragma unroll
        for (int nt = 0; nt < 8; nt++)
            #pragma unroll
            for (int q = 0; q < 4; q++) acc[mt][nt][q] = 0.f;

    for (int c0 = 0; c0 < 512; c0 += 16) {
        #pragma unroll
        for (int m = 0; m < 4; m++) {
            int idx = m * 256 + tid;
            if (idx < 512) {
                int mat = idx >> 8, r = (idx >> 4) & 15, q = idx & 15;
                const uint16_t* src = mat ? pl : ph;
                uint16_t* dst = mat ? Al : Ah;
                *(uint4*)&dst[r * LDA + q * 8] =
                    *(const uint4*)&src[(size_t)(c0 + r) * NPTS + n0 + q * 8];
            } else {
                int j = idx - 512;
                int mat = j >> 8, row = (j >> 1) & 127, q = j & 1;
                const uint16_t* src = mat ? g_w5l : g_w5h;
                uint16_t* dst = mat ? Bl : Bh;
                *(uint4*)&dst[row * LDB + q * 8] =
                    *(const uint4*)&src[(size_t)(o0 + row) * 512 + c0 + q * 8];
            }
        }
        __syncthreads();
        #pragma unroll
        for (int pass = 0; pass < 3; pass++) {
            const uint16_t* A = (pass == 1) ? Al : Ah;
            const uint16_t* B = (pass == 2) ? Bl : Bh;
            uint32_t af[2][4];
            #pragma unroll
            for (int mt = 0; mt < 2; mt++) {
                int krow = ((sub & 2) ? 8 : 0) + Lr;
                int mcol = wm * 32 + mt * 16 + ((sub & 1) ? 8 : 0);
                ldsm4t(af[mt][0], af[mt][1], af[mt][2], af[mt][3],
                       sptr(A + krow * LDA + mcol));
            }
            uint32_t bf[8][2];
            #pragma unroll
            for (int u = 0; u < 4; u++) {
                int orow = wn * 64 + u * 16 + ((sub & 2) ? 8 : 0) + Lr;
                int kcol = (sub & 1) ? 8 : 0;
                uint32_t r0, r1, r2, r3;
                ldsm4(r0, r1, r2, r3, sptr(B + orow * LDB + kcol));
                bf[2 * u][0] = r0; bf[2 * u][1] = r1;
                bf[2 * u + 1][0] = r2; bf[2 * u + 1][1] = r3;
            }
            #pragma unroll
            for (int nt = 0; nt < 8; nt++) {
                mma_bf16(acc[0][nt], af[0], bf[nt][0], bf[nt][1]);
                mma_bf16(acc[1][nt], af[1], bf[nt][0], bf[nt][1]);
            }
        }
        __syncthreads();
    }
    // epilogue: BN + lrelu, then per-block (max,sum) per channel
    int t = lane & 3;
    float pm[16], ps[16];
    #pragma unroll
    for (int i = 0; i < 16; i++) { pm[i] = -FLT_MAX; ps[i] = 0.f; }
    #pragma unroll
    for (int nt = 0; nt < 8; nt++) {
        int o = o0 + wn * 64 + nt * 8 + 2 * t;
        float sc0 = gam[o] * BN_RSQ, bi0 = bet[o];
        float sc1 = gam[o + 1] * BN_RSQ, bi1 = bet[o + 1];
        #pragma unroll
        for (int mt = 0; mt < 2; mt++) {
            float h0 = lrelu(fmaf(acc[mt][nt][0], sc0, bi0));
            float h1 = lrelu(fmaf(acc[mt][nt][1], sc1, bi1));
            float h2 = lrelu(fmaf(acc[mt][nt][2], sc0, bi0));
            float h3 = lrelu(fmaf(acc[mt][nt][3], sc1, bi1));
            pm[nt * 2] = fmaxf(pm[nt * 2], fmaxf(h0, h2));
            ps[nt * 2] += h0 + h2;
            pm[nt * 2 + 1] = fmaxf(pm[nt * 2 + 1], fmaxf(h1, h3));
            ps[nt * 2 + 1] += h1 + h3;
        }
    }
    #pragma unroll
    for (int i = 0; i < 16; i++) {
        #pragma unroll
        for (int off = 4; off <= 16; off <<= 1) {
            pm[i] = fmaxf(pm[i], __shfl_xor_sync(FULL, pm[i], off));
            ps[i] += __shfl_xor_sync(FULL, ps[i], off);
        }
    }
    if (lane < 4) {      // g==0, t=lane: owns cols nt*8 + 2*lane + p
        #pragma unroll
        for (int nt = 0; nt < 8; nt++) {
            #pragma unroll
            for (int p = 0; p < 2; p++) {
                int cc = nt * 8 + 2 * lane + p;
                sm_max[warp][cc] = pm[nt * 2 + p];
                sm_sum[warp][cc] = ps[nt * 2 + p];
            }
        }
    }
    __syncthreads();
    if (tid < 128) {
        int col = tid;
        int w0 = (col >> 6) * 4, cc = col & 63;
        float m = sm_max[w0][cc], s = sm_sum[w0][cc];
        #pragma unroll
        for (int w = 1; w < 4; w++) {
            m = fmaxf(m, sm_max[w0 + w][cc]);
            s += sm_sum[w0 + w][cc];
        }
        size_t base = (size_t)(b * 16 + blockIdx.x) * 1024 + o0 + col;
        g_pmax[base] = m;
        g_psum[base] = s;
    }
}

// ---------------- fused top-K: threshold (chunk maxes) + compact + select --
__global__ void k_topk() {
    __shared__ float sv[8][CAP];
    __shared__ int   si[8][CAP];
    const unsigned FULL = 0xffffffffu;
    int lane = threadIdx.x & 31, warp = threadIdx.x >> 5;
    int row = blockIdx.x * 8 + warp;
    const float* drow = g_D + (size_t)row * NPTS;

    // Te = 20th largest of 32 precomputed 64-col chunk maxes (<= true 20th)
    float v = g_smax[(size_t)row * 32 + lane];
    #pragma unroll
    for (int k = 2; k <= 32; k <<= 1) {
        #pragma unroll
        for (int j = k >> 1; j > 0; j >>= 1) {
            float o = __shfl_xor_sync(FULL, v, j);
            bool takeMax = (((lane & k) == 0) == ((lane & j) == 0));
            v = takeMax ? fmaxf(v, o) : fminf(v, o);
        }
    }
    float Te = __shfl_sync(FULL, v, KNN - 1);

    // single-pass compact into smem
    unsigned lmask = (1u << lane) - 1u;
    unsigned cnt = 0;
    #pragma unroll 2
    for (int t = 0; t < NPTS / 128; t++) {
        int jb = t * 128 + lane * 4;
        float4 q = *(const float4*)&drow[jb];
        float vals[4] = {q.x, q.y, q.z, q.w};
        #pragma unroll
        for (int m = 0; m < 4; m++) {
            bool pass = vals[m] >= Te;
            unsigned mk = __ballot_sync(FULL, pass);
            if (pass) {
                unsigned pos = cnt + __popc(mk & lmask);
                if (pos < CAP) { sv[warp][pos] = vals[m]; si[warp][pos] = jb + m; }
            }
            cnt += __popc(mk);
        }
    }
    __syncwarp();

    if (cnt <= CAP) {
        float lv[8]; int li[8];
        #pragma unroll
        for (int q = 0; q < 8; q++) {
            int p = q * 32 + lane;
            bool in = p < (int)cnt;
            lv[q] = in ? sv[warp][p] : -FLT_MAX;
            li[q] = in ? si[warp][p] : 0x7FFFFFFF;
        }
        #pragma unroll 1
        for (int k = 0; k < KNN; k++) {
            float bv = -FLT_MAX; int bi = 0x7FFFFFFF, bq = 0;
            #pragma unroll
            for (int q = 0; q < 8; q++) {
                if (lv[q] > bv || (lv[q] == bv && li[q] < bi)) {
                    bv = lv[q]; bi = li[q]; bq = q;
                }
            }
            float wv = bv; int wi = bi;
            #pragma unroll
            for (int s = 16; s > 0; s >>= 1) {
                float ov = __shfl_xor_sync(FULL, wv, s);
                int   oi = __shfl_xor_sync(FULL, wi, s);
                if (ov > wv || (ov == wv && oi < wi)) { wv = ov; wi = oi; }
            }
            if (lane == 0) g_knn[(size_t)row * KNN + k] = wi;
            if (bv == wv && bi == wi) { lv[bq] = -FLT_MAX; li[bq] = 0x7FFFFFFF; }
        }
    } else {
        // exact fallback: full-row scan, per-lane sorted 20-list + 20 pops
        float arr[KNN]; int ai[KNN];
        #pragma unroll
        for (int q = 0; q < KNN; q++) { arr[q] = -FLT_MAX; ai[q] = 0x7FFFFFFF; }
        #pragma unroll 1
        for (int t = 0; t < NPTS / 128; t++) {
            int jb = t * 128 + lane * 4;
            float4 v4 = *(const float4*)&drow[jb];
            float vv[4] = {v4.x, v4.y, v4.z, v4.w};
            #pragma unroll
            for (int m = 0; m < 4; m++) {
                float vx = vv[m];
                if (vx > arr[0]) {
                    arr[0] = vx; ai[0] = jb + m;
                    #pragma unroll
                    for (int q = 0; q < KNN - 1; q++) {
                        if (arr[q + 1] < arr[q]) {
                            float tv = arr[q]; arr[q] = arr[q + 1]; arr[q + 1] = tv;
                            int ti = ai[q]; ai[q] = ai[q + 1]; ai[q + 1] = ti;
                        }
                    }
                }
            }
        }
        #pragma unroll 1
        for (int k = 0; k < KNN; k++) {
            float cvv = arr[KNN - 1]; int cii = ai[KNN - 1];
            float wv = cvv; int wi = cii;
            #pragma unroll
            for (int s = 16; s > 0; s >>= 1) {
                float ov = __shfl_xor_sync(FULL, wv, s);
                int   oi = __shfl_xor_sync(FULL, wi, s);
                if (ov > wv || (ov == wv && oi < wi)) { wv = ov; wi = oi; }
            }
            if (lane == 0) g_knn[(size_t)row * KNN + k] = wi;
            if (cii == wi) {
                #pragma unroll
                for (int q = KNN - 1; q > 0; q--) { arr[q] = arr[q - 1]; ai[q] = ai[q - 1]; }
                arr[0] = -FLT_MAX; ai[0] = 0x7FFFFFFF;
            }
        }
    }
}

// ---------------- Y = W2 X, Z = (W1-W2) X (fp32) ---------------------------
__global__ void k_yz(const float* __restrict__ feat, const float* __restrict__ W,
                     int C, int Cout, int bstr) {
    __shared__ float As[16][64];
    __shared__ float B1[16][64];
    __shared__ float B2[16][64];
    int b = blockIdx.z;
    int n0 = blockIdx.x * 64, o0 = blockIdx.y * 64;
    const float* fb = feat + (size_t)b * bstr;
    int tx = threadIdx.x & 15, ty = threadIdx.x >> 4;
    float aU[4][4] = {}, aY[4][4] = {};
    for (int c0 = 0; c0 < C; c0 += 16) {
        for (int e = threadIdx.x; e < 1024; e += 256) {
            int kk = e >> 6, nn = e & 63;
            int c = c0 + kk;
            As[kk][nn] = (c < C) ? fb[(size_t)c * NPTS + n0 + nn] : 0.f;
        }
        for (int e = threadIdx.x; e < 1024; e += 256) {
            int kk = e & 15, oo = e >> 4;
            int c = c0 + kk;
            float w1 = 0.f, w2 = 0.f;
            if (c < C) {
                const float* wr = W + (size_t)(o0 + oo) * (2 * C);
                w1 = wr[c]; w2 = wr[C + c];
            }
            B1[kk][oo] = w1; B2[kk][oo] = w2;
        }
        __syncthreads();
        #pragma unroll
        for (int kk = 0; kk < 16; kk++) {
            float4 a4 = *(const float4*)&As[kk][ty * 4];
            float4 b14 = *(const float4*)&B1[kk][tx * 4];
            float4 b24 = *(const float4*)&B2[kk][tx * 4];
            float av[4] = {a4.x, a4.y, a4.z, a4.w};
            float b1v[4] = {b14.x, b14.y, b14.z, b14.w};
            float b2v[4] = {b24.x, b24.y, b24.z, b24.w};
            #pragma unroll
            for (int r = 0; r < 4; r++)
                #pragma unroll
                for (int s = 0; s < 4; s++) {
                    aU[r][s] = fmaf(av[r], b1v[s], aU[r][s]);
                    aY[r][s] = fmaf(av[r], b2v[s], aY[r][s]);
                }
        }
        __syncthreads();
    }
    #pragma unroll
    for (int r = 0; r < 4; r++) {
        int n = n0 + ty * 4 + r;
        size_t base = ((size_t)b * NPTS + n) * 256 + o0 + tx * 4;
        float4 y, z;
        y.x = aY[r][0]; y.y = aY[r][1]; y.z = aY[r][2]; y.w = aY[r][3];
        z.x = aU[r][0] - y.x; z.y = aU[r][1] - y.y;
        z.z = aU[r][2] - y.z; z.w = aU[r][3] - y.w;
        *(float4*)&g_Y[base] = y;
        *(float4*)&g_Z[base] = z;
    }
}

// ---------------- gather-max + BN + lrelu -> xcat + bf16 mirrors -----------
__global__ void k_gather(float* __restrict__ out, const float* __restrict__ gam,
                         const float* __restrict__ bet, int Cout, int co) {
    __shared__ int   sidx[32 * KNN];
    __shared__ float sout[256 * 33];
    int b = blockIdx.y, n0 = blockIdx.x * 32;
    for (int e = threadIdx.x; e < 32 * KNN; e += blockDim.x)
        sidx[e] = g_knn[((size_t)b * NPTS + n0) * KNN + e];
    __syncthreads();
    int o = threadIdx.x;
    float sc = gam[o] * BN_RSQ, bi = bet[o];
    const float* Yb = g_Y + (size_t)b * NPTS * 256;
    const float* Zb = g_Z + (size_t)b * NPTS * 256;
    for (int nn = 0; nn < 32; nn++) {
        float m = -FLT_MAX;
        #pragma unroll
        for (int k = 0; k < KNN; k++) {
            int j = sidx[nn * KNN + k];
            m = fmaxf(m, Yb[(size_t)j * 256 + o]);
        }
        float v = Zb[(size_t)(n0 + nn) * 256 + o] + m;
        v = lrelu(fmaf(v, sc, bi));
        sout[o * 33 + nn] = v;
    }
    __syncthreads();
    float* ob = out + (size_t)b * CAT_BSTR;
    for (int e = threadIdx.x; e < Cout * 32; e += blockDim.x) {
        int oo = e >> 5, nn = e & 31;
        float v = sout[oo * 33 + nn];
        ob[(size_t)oo * NPTS + n0 + nn] = v;
        uint16_t h, l;
        split_bf16(v, h, l);
        size_t bidx = ((size_t)b * 512 + co + oo) * NPTS + n0 + nn;
        g_ch[bidx] = h;
        g_cl[bidx] = l;
    }
}

// ---------------- final pool from conv5 partials -> g_f --------------------
__global__ void k_pool2() {
    int b = blockIdx.y;
    int o = blockIdx.x * 256 + threadIdx.x;
    float m = -FLT_MAX, s = 0.f;
    #pragma unroll
    for (int nt = 0; nt < 16; nt++) {
        size_t base = (size_t)(b * 16 + nt) * 1024 + o;
        m = fmaxf(m, g_pmax[base]);
        s += g_psum[base];
    }
    g_f[b * 2048 + o] = m;
    g_f[b * 2048 + 1024 + o] = s * (1.0f / NPTS);
}

// ---------------- fc1: 2048->512, BN + lrelu -------------------------------
__global__ void k_fc1(const float* __restrict__ fw, const float* __restrict__ fb,
                      const float* __restrict__ gam, const float* __restrict__ bet) {
    int b = blockIdx.y;
    int w = threadIdx.x >> 5, lane = threadIdx.x & 31;
    int o = blockIdx.x * 8 + w;
    const float* f = g_f + b * 2048;
    const float* wr = fw + (size_t)o * 2048;
    float acc = 0.f;
    for (int c = lane; c < 2048; c += 32) acc = fmaf(f[c], wr[c], acc);
    #pragma unroll
    for (int s = 16; s > 0; s >>= 1) acc += __shfl_xor_sync(0xffffffffu, acc, s);
    if (lane == 0) {
        float v = acc + fb[o];
        v = lrelu(fmaf(v, gam[o] * BN_RSQ, bet[o]));
        g_fc1[b * 512 + o] = v;
    }
}

// ---------------- fc2: 512->256, BN (no lrelu) -> d_out --------------------
__global__ void k_fc2(const float* __restrict__ fw, const float* __restrict__ fb,
                      const float* __restrict__ gam, const float* __restrict__ bet,
                      float* __restrict__ out) {
    int b = blockIdx.y;
    int w = threadIdx.x >> 5, lane = threadIdx.x & 31;
    int o = blockIdx.x * 8 + w;
    const float* f = g_fc1 + b * 512;
    const float* wr = fw + (size_t)o * 512;
    float acc = 0.f;
    for (int c = lane; c < 512; c += 32) acc = fmaf(f[c], wr[c], acc);
    #pragma unroll
    for (int s = 16; s > 0; s >>= 1) acc += __shfl_xor_sync(0xffffffffu, acc, s);
    if (lane == 0) {
        float v = acc + fb[o];
        out[b * 256 + o] = fmaf(v, gam[o] * BN_RSQ, bet[o]);
    }
}

// ---------------- driver ---------------------------------------------------
static void run_edge(const float* feat, int C, int bstr,
                     const uint16_t* dh, const uint16_t* dl, int Ceff, int bfstr,
                     const float* W, const float* gam, const float* bet,
                     float* out, int Cout, int co) {
    k_xx<<<(BATCH * NPTS + 255) / 256, 256>>>(feat, C, bstr);
    k_dist_mma<<<dim3(NPTS / 128, NPTS / 128, BATCH), 256>>>(dh, dl, Ceff, bfstr);
    k_topk<<<BATCH * NPTS / 8, 256>>>();
    k_yz<<<dim3(NPTS / 64, Cout / 64, BATCH), 256>>>(feat, W, C, Cout, bstr);
    k_gather<<<dim3(NPTS / 32, BATCH), Cout>>>(out, gam, bet, Cout, co);
}

extern "C" void kernel_launch(void* const* d_in, const int* in_sizes, int n_in,
                              void* d_out, int out_size) {
    const float* pts = (const float*)d_in[0];
    const float* w1 = (const float*)d_in[1];
    const float* g1 = (const float*)d_in[2];
    const float* b1 = (const float*)d_in[3];
    const float* w2 = (const float*)d_in[4];
    const float* g2 = (const float*)d_in[5];
    const float* b2 = (const float*)d_in[6];
    const float* w3 = (const float*)d_in[7];
    const float* g3 = (const float*)d_in[8];
    const float* b3 = (const float*)d_in[9];
    const float* w4 = (const float*)d_in[10];
    const float* g4 = (const float*)d_in[11];
    const float* b4 = (const float*)d_in[12];
    const float* w5 = (const float*)d_in[13];
    const float* g5 = (const float*)d_in[14];
    const float* b5 = (const float*)d_in[15];
    const float* fw1 = (const float*)d_in[16];
    const float* fb1 = (const float*)d_in[17];
    const float* g6 = (const float*)d_in[18];
    const float* b6 = (const float*)d_in[19];
    const float* fw2 = (const float*)d_in[20];
    const float* fb2 = (const float*)d_in[21];
    const float* g7 = (const float*)d_in[22];
    const float* b7 = (const float*)d_in[23];

    float *x0, *xcat;
    uint16_t *x0h, *x0l, *ch, *cl;
    cudaGetSymbolAddress((void**)&x0, g_x0);
    cudaGetSymbolAddress((void**)&xcat, g_xcat);
    cudaGetSymbolAddress((void**)&x0h, g_x0h);
    cudaGetSymbolAddress((void**)&x0l, g_x0l);
    cudaGetSymbolAddress((void**)&ch, g_ch);
    cudaGetSymbolAddress((void**)&cl, g_cl);
    float* x1 = xcat;                  // ch 0..63
    float* x2 = xcat + 64 * NPTS;      // ch 64..127
    float* x3 = xcat + 128 * NPTS;     // ch 128..255
    float* x4 = xcat + 256 * NPTS;     // ch 256..511

    k_transpose<<<(BATCH * NPTS + 255) / 256, 256>>>(pts);
    run_edge(x0, 3,   3 * NPTS, x0h, x0l, 16, 16 * NPTS,
             w1, g1, b1, x1, 64, 0);
    run_edge(x1, 64,  CAT_BSTR, ch,              cl,              64,  CAT_BSTR,
             w2, g2, b2, x2, 64, 64);
    run_edge(x2, 64,  CAT_BSTR, ch + 64 * NPTS,  cl + 64 * NPTS,  64,  CAT_BSTR,
             w3, g3, b3, x3, 128, 128);
    run_edge(x3, 128, CAT_BSTR, ch + 128 * NPTS, cl + 128 * NPTS, 128, CAT_BSTR,
             w4, g4, b4, x4, 256, 256);
    k_cvt_w5<<<(1024 * 512 + 255) / 256, 256>>>(w5);
    k_conv5_mma<<<dim3(NPTS / 128, 1024 / 128, BATCH), 256>>>(g5, b5);
    k_pool2<<<dim3(1024 / 256, BATCH), 256>>>();
    k_fc1<<<dim3(512 / 8, BATCH), 256>>>(fw1, fb1, g6, b6);
    k_fc2<<<dim3(256 / 8, BATCH), 256>>>(fw2, fb2, g7, b7, (float*)d_out);
}

// round 12
// speedup vs baseline: 3.0421x; 1.1160x over previous
#include <cuda_runtime.h>
#include <cuda_bf16.h>
#include <cfloat>
#include <cstdint>
#include <cstddef>

#define NPTS 2048
#define BATCH 4
#define KNN 20
#define CAP 256

// ---------------- scratch (device globals; no allocation allowed) ----------
__device__ float g_x0[BATCH * 3 * NPTS];
__device__ float g_xcat[(size_t)BATCH * 512 * NPTS];     // fp32 concat feats
__device__ uint16_t g_x0h[BATCH * 16 * NPTS];            // bf16 hi of x0, Cpad=16
__device__ uint16_t g_x0l[BATCH * 16 * NPTS];            // bf16 lo
__device__ uint16_t g_ch[(size_t)BATCH * 512 * NPTS];    // bf16 hi of xcat
__device__ uint16_t g_cl[(size_t)BATCH * 512 * NPTS];    // bf16 lo
__device__ uint16_t g_w5h[1024 * 512];
__device__ uint16_t g_w5l[1024 * 512];
__device__ float g_xx[BATCH * NPTS];
__device__ float g_D[(size_t)BATCH * NPTS * NPTS];       // 64 MB
__device__ float g_smax[(size_t)BATCH * NPTS * 32];      // per-row 64-col chunk maxes
__device__ int   g_knn[BATCH * NPTS * KNN];
__device__ int   g_cnt[BATCH * NPTS];
__device__ float g_Y[BATCH * NPTS * 256];
__device__ float g_Z[BATCH * NPTS * 256];
__device__ float g_pmax[BATCH * 16 * 1024];              // conv5 partial max
__device__ float g_psum[BATCH * 16 * 1024];              // conv5 partial sum
__device__ float g_f[BATCH * 2048];
__device__ float g_fc1[BATCH * 512];

__device__ __forceinline__ float lrelu(float v) { return v > 0.f ? v : 0.2f * v; }
#define BN_RSQ 0.99999500003749968750f
#define CAT_BSTR (512 * NPTS)
#define LDA 136   /* [k][m] tile row stride (halves) */
#define LDB 24    /* conv5 W tile [o][k] row stride (halves) */

__device__ __forceinline__ void split_bf16(float x, uint16_t& h, uint16_t& l) {
    __nv_bfloat16 bh = __float2bfloat16(x);
    float r = x - __bfloat162float(bh);
    __nv_bfloat16 bl = __float2bfloat16(r);
    h = *reinterpret_cast<uint16_t*>(&bh);
    l = *reinterpret_cast<uint16_t*>(&bl);
}

__device__ __forceinline__ void mma_bf16(float c[4], const uint32_t a[4],
                                         uint32_t b0, uint32_t b1) {
    asm volatile(
        "mma.sync.aligned.m16n8k16.row.col.f32.bf16.bf16.f32 "
        "{%0,%1,%2,%3}, {%4,%5,%6,%7}, {%8,%9}, {%0,%1,%2,%3};"
        : "+f"(c[0]), "+f"(c[1]), "+f"(c[2]), "+f"(c[3])
        : "r"(a[0]), "r"(a[1]), "r"(a[2]), "r"(a[3]), "r"(b0), "r"(b1));
}

__device__ __forceinline__ uint32_t sptr(const void* p) {
    return (uint32_t)__cvta_generic_to_shared(p);
}
__device__ __forceinline__ void ldsm4t(uint32_t& r0, uint32_t& r1,
                                       uint32_t& r2, uint32_t& r3, uint32_t a) {
    asm volatile("ldmatrix.sync.aligned.m8n8.x4.trans.shared.b16 {%0,%1,%2,%3}, [%4];"
                 : "=r"(r0), "=r"(r1), "=r"(r2), "=r"(r3) : "r"(a));
}
__device__ __forceinline__ void ldsm4(uint32_t& r0, uint32_t& r1,
                                      uint32_t& r2, uint32_t& r3, uint32_t a) {
    asm volatile("ldmatrix.sync.aligned.m8n8.x4.shared.b16 {%0,%1,%2,%3}, [%4];"
                 : "=r"(r0), "=r"(r1), "=r"(r2), "=r"(r3) : "r"(a));
}

// ---------------- transpose points + bf16 split (Cpad=16) ------------------
__global__ void k_transpose(const float* __restrict__ pts) {
    int i = blockIdx.x * blockDim.x + threadIdx.x;
    if (i < BATCH * NPTS) {
        int b = i / NPTS, n = i % NPTS;
        #pragma unroll
        for (int c = 0; c < 3; c++) {
            float v = pts[(b * NPTS + n) * 3 + c];
            g_x0[(b * 3 + c) * NPTS + n] = v;
            uint16_t h, l;
            split_bf16(v, h, l);
            g_x0h[(b * 16 + c) * NPTS + n] = h;
            g_x0l[(b * 16 + c) * NPTS + n] = l;
        }
        #pragma unroll
        for (int c = 3; c < 16; c++) {
            g_x0h[(b * 16 + c) * NPTS + n] = 0;
            g_x0l[(b * 16 + c) * NPTS + n] = 0;
        }
    }
}

// ---------------- row norms (fp32 exact) -----------------------------------
__global__ void k_xx(const float* __restrict__ feat, int C, int bstr) {
    int i = blockIdx.x * blockDim.x + threadIdx.x;
    if (i < BATCH * NPTS) {
        int b = i / NPTS, n = i % NPTS;
        const float* f = feat + (size_t)b * bstr + n;
        float s = 0.f;
        for (int c = 0; c < C; c++) { float v = f[(size_t)c * NPTS]; s = fmaf(v, v, s); }
        g_xx[i] = s;
    }
}

// ---------------- w5 bf16 split --------------------------------------------
__global__ void k_cvt_w5(const float* __restrict__ w5) {
    int i = blockIdx.x * blockDim.x + threadIdx.x;
    if (i < 1024 * 512) {
        uint16_t h, l;
        split_bf16(w5[i], h, l);
        g_w5h[i] = h; g_w5l[i] = l;
    }
}

// ---------------- distance GEMM via split-bf16 mma + ldmatrix --------------
// Also emits per-row 64-col chunk maxes to g_smax (for single-pass topk).
__global__ __launch_bounds__(256, 2) void k_dist_mma(
        const uint16_t* __restrict__ srch, const uint16_t* __restrict__ srcl,
        int Ceff, int bstr) {
    __shared__ uint16_t Ah[16 * LDA], Al[16 * LDA];
    __shared__ uint16_t Bh[16 * LDA], Bl[16 * LDA];
    const unsigned FULL = 0xffffffffu;
    int b = blockIdx.z;
    int i0 = blockIdx.y * 128, j0 = blockIdx.x * 128;
    const uint16_t* ph = srch + (size_t)b * bstr;
    const uint16_t* pl = srcl + (size_t)b * bstr;
    int tid = threadIdx.x, lane = tid & 31, warp = tid >> 5;
    int wm = warp & 3, wn = warp >> 2;
    int sub = lane >> 3, Lr = lane & 7;
    float acc[2][8][4];
    #pragma unroll
    for (int mt = 0; mt < 2; mt++)
        #pragma unroll
        for (int nt = 0; nt < 8; nt++)
            #pragma unroll
            for (int q = 0; q < 4; q++) acc[mt][nt][q] = 0.f;

    for (int c0 = 0; c0 < Ceff; c0 += 16) {
        #pragma unroll
        for (int m = 0; m < 4; m++) {
            int idx = m * 256 + tid;
            int mat = idx >> 8, r = (idx >> 4) & 15, q = idx & 15;
            const uint16_t* src = (mat & 1) ? pl : ph;
            int base = (mat & 2) ? j0 : i0;
            uint16_t* dst = (mat == 0) ? Ah : (mat == 1) ? Al : (mat == 2) ? Bh : Bl;
            *(uint4*)&dst[r * LDA + q * 8] =
                *(const uint4*)&src[(size_t)(c0 + r) * NPTS + base + q * 8];
        }
        __syncthreads();
        #pragma unroll
        for (int pass = 0; pass < 3; pass++) {
            const uint16_t* A = (pass == 1) ? Al : Ah;
            const uint16_t* B = (pass == 2) ? Bl : Bh;
            uint32_t af[2][4];
            #pragma unroll
            for (int mt = 0; mt < 2; mt++) {
                int krow = ((sub & 2) ? 8 : 0) + Lr;
                int mcol = wm * 32 + mt * 16 + ((sub & 1) ? 8 : 0);
                ldsm4t(af[mt][0], af[mt][1], af[mt][2], af[mt][3],
                       sptr(A + krow * LDA + mcol));
            }
            uint32_t bf[8][2];
            #pragma unroll
            for (int u = 0; u < 4; u++) {
                int krow = ((sub & 1) ? 8 : 0) + Lr;
                int ncol = wn * 64 + u * 16 + ((sub & 2) ? 8 : 0);
                uint32_t r0, r1, r2, r3;
                ldsm4t(r0, r1, r2, r3, sptr(B + krow * LDA + ncol));
                bf[2 * u][0] = r0; bf[2 * u][1] = r1;
                bf[2 * u + 1][0] = r2; bf[2 * u + 1][1] = r3;
            }
            #pragma unroll
            for (int nt = 0; nt < 8; nt++) {
                mma_bf16(acc[0][nt], af[0], bf[nt][0], bf[nt][1]);
                mma_bf16(acc[1][nt], af[1], bf[nt][0], bf[nt][1]);
            }
        }
        __syncthreads();
    }
    // epilogue: 2*acc - xi - xj -> g_D, plus warp 64-col chunk max -> g_smax
    int g = lane >> 2, t = lane & 3;
    #pragma unroll
    for (int mt = 0; mt < 2; mt++) {
        int r0 = i0 + wm * 32 + mt * 16 + g;
        int r1 = r0 + 8;
        float xi0 = g_xx[b * NPTS + r0];
        float xi1 = g_xx[b * NPTS + r1];
        float m0 = -FLT_MAX, m1 = -FLT_MAX;
        #pragma unroll
        for (int nt = 0; nt < 8; nt++) {
            int j = j0 + wn * 64 + nt * 8 + 2 * t;
            float xj0 = g_xx[b * NPTS + j];
            float xj1 = g_xx[b * NPTS + j + 1];
            float2 v0, v1;
            v0.x = 2.f * acc[mt][nt][0] - xi0 - xj0;
            v0.y = 2.f * acc[mt][nt][1] - xi0 - xj1;
            v1.x = 2.f * acc[mt][nt][2] - xi1 - xj0;
            v1.y = 2.f * acc[mt][nt][3] - xi1 - xj1;
            m0 = fmaxf(m0, fmaxf(v0.x, v0.y));
            m1 = fmaxf(m1, fmaxf(v1.x, v1.y));
            *(float2*)&g_D[((size_t)b * NPTS + r0) * NPTS + j] = v0;
            *(float2*)&g_D[((size_t)b * NPTS + r1) * NPTS + j] = v1;
        }
        m0 = fmaxf(m0, __shfl_xor_sync(FULL, m0, 1));
        m0 = fmaxf(m0, __shfl_xor_sync(FULL, m0, 2));
        m1 = fmaxf(m1, __shfl_xor_sync(FULL, m1, 1));
        m1 = fmaxf(m1, __shfl_xor_sync(FULL, m1, 2));
        if (t == 0) {
            int ch = (j0 >> 6) + wn;
            g_smax[(size_t)(b * NPTS + r0) * 32 + ch] = m0;
            g_smax[(size_t)(b * NPTS + r1) * 32 + ch] = m1;
        }
    }
}

// ---------------- conv5 via split-bf16 mma + fused partial pooling ---------
__global__ __launch_bounds__(256, 2) void k_conv5_mma(
        const float* __restrict__ gam, const float* __restrict__ bet) {
    __shared__ uint16_t Ah[16 * LDA], Al[16 * LDA];
    __shared__ uint16_t Bh[128 * LDB], Bl[128 * LDB];
    __shared__ float sm_max[8][64];
    __shared__ float sm_sum[8][64];
    const unsigned FULL = 0xffffffffu;
    int b = blockIdx.z;
    int n0 = blockIdx.x * 128, o0 = blockIdx.y * 128;
    const uint16_t* ph = g_ch + (size_t)b * CAT_BSTR;
    const uint16_t* pl = g_cl + (size_t)b * CAT_BSTR;
    int tid = threadIdx.x, lane = tid & 31, warp = tid >> 5;
    int wm = warp & 3, wn = warp >> 2;
    int sub = lane >> 3, Lr = lane & 7;
    float acc[2][8][4];
    #pragma unroll
    for (int mt = 0; mt < 2; mt++)
        #pragma unroll
        for (int nt = 0; nt < 8; nt++)
            #pragma unroll
            for (int q = 0; q < 4; q++) acc[mt][nt][q] = 0.f;

    for (int c0 = 0; c0 < 512; c0 += 16) {
        #pragma unroll
        for (int m = 0; m < 4; m++) {
            int idx = m * 256 + tid;
            if (idx < 512) {
                int mat = idx >> 8, r = (idx >> 4) & 15, q = idx & 15;
                const uint16_t* src = mat ? pl : ph;
                uint16_t* dst = mat ? Al : Ah;
                *(uint4*)&dst[r * LDA + q * 8] =
                    *(const uint4*)&src[(size_t)(c0 + r) * NPTS + n0 + q * 8];
            } else {
                int j = idx - 512;
                int mat = j >> 8, row = (j >> 1) & 127, q = j & 1;
                const uint16_t* src = mat ? g_w5l : g_w5h;
                uint16_t* dst = mat ? Bl : Bh;
                *(uint4*)&dst[row * LDB + q * 8] =
                    *(const uint4*)&src[(size_t)(o0 + row) * 512 + c0 + q * 8];
            }
        }
        __syncthreads();
        #pragma unroll
        for (int pass = 0; pass < 3; pass++) {
            const uint16_t* A = (pass == 1) ? Al : Ah;
            const uint16_t* B = (pass == 2) ? Bl : Bh;
            uint32_t af[2][4];
            #pragma unroll
            for (int mt = 0; mt < 2; mt++) {
                int krow = ((sub & 2) ? 8 : 0) + Lr;
                int mcol = wm * 32 + mt * 16 + ((sub & 1) ? 8 : 0);
                ldsm4t(af[mt][0], af[mt][1], af[mt][2], af[mt][3],
                       sptr(A + krow * LDA + mcol));
            }
            uint32_t bf[8][2];
            #pragma unroll
            for (int u = 0; u < 4; u++) {
                int orow = wn * 64 + u * 16 + ((sub & 2) ? 8 : 0) + Lr;
                int kcol = (sub & 1) ? 8 : 0;
                uint32_t r0, r1, r2, r3;
                ldsm4(r0, r1, r2, r3, sptr(B + orow * LDB + kcol));
                bf[2 * u][0] = r0; bf[2 * u][1] = r1;
                bf[2 * u + 1][0] = r2; bf[2 * u + 1][1] = r3;
            }
            #pragma unroll
            for (int nt = 0; nt < 8; nt++) {
                mma_bf16(acc[0][nt], af[0], bf[nt][0], bf[nt][1]);
                mma_bf16(acc[1][nt], af[1], bf[nt][0], bf[nt][1]);
            }
        }
        __syncthreads();
    }
    // epilogue: BN + lrelu, then per-block (max,sum) per channel
    int t = lane & 3;
    float pm[16], ps[16];
    #pragma unroll
    for (int i = 0; i < 16; i++) { pm[i] = -FLT_MAX; ps[i] = 0.f; }
    #pragma unroll
    for (int nt = 0; nt < 8; nt++) {
        int o = o0 + wn * 64 + nt * 8 + 2 * t;
        float sc0 = gam[o] * BN_RSQ, bi0 = bet[o];
        float sc1 = gam[o + 1] * BN_RSQ, bi1 = bet[o + 1];
        #pragma unroll
        for (int mt = 0; mt < 2; mt++) {
            float h0 = lrelu(fmaf(acc[mt][nt][0], sc0, bi0));
            float h1 = lrelu(fmaf(acc[mt][nt][1], sc1, bi1));
            float h2 = lrelu(fmaf(acc[mt][nt][2], sc0, bi0));
            float h3 = lrelu(fmaf(acc[mt][nt][3], sc1, bi1));
            pm[nt * 2] = fmaxf(pm[nt * 2], fmaxf(h0, h2));
            ps[nt * 2] += h0 + h2;
            pm[nt * 2 + 1] = fmaxf(pm[nt * 2 + 1], fmaxf(h1, h3));
            ps[nt * 2 + 1] += h1 + h3;
        }
    }
    #pragma unroll
    for (int i = 0; i < 16; i++) {
        #pragma unroll
        for (int off = 4; off <= 16; off <<= 1) {
            pm[i] = fmaxf(pm[i], __shfl_xor_sync(FULL, pm[i], off));
            ps[i] += __shfl_xor_sync(FULL, ps[i], off);
        }
    }
    if (lane < 4) {
        #pragma unroll
        for (int nt = 0; nt < 8; nt++) {
            #pragma unroll
            for (int p = 0; p < 2; p++) {
                int cc = nt * 8 + 2 * lane + p;
                sm_max[warp][cc] = pm[nt * 2 + p];
                sm_sum[warp][cc] = ps[nt * 2 + p];
            }
        }
    }
    __syncthreads();
    if (tid < 128) {
        int col = tid;
        int w0 = (col >> 6) * 4, cc = col & 63;
        float m = sm_max[w0][cc], s = sm_sum[w0][cc];
        #pragma unroll
        for (int w = 1; w < 4; w++) {
            m = fmaxf(m, sm_max[w0 + w][cc]);
            s += sm_sum[w0 + w][cc];
        }
        size_t base = (size_t)(b * 16 + blockIdx.x) * 1024 + o0 + col;
        g_pmax[base] = m;
        g_psum[base] = s;
    }
}

// ---------------- top-K main: threshold + compact + select (no fallback) ---
__global__ __launch_bounds__(256) void k_topk() {
    __shared__ float sv[8][CAP];
    __shared__ int   si[8][CAP];
    const unsigned FULL = 0xffffffffu;
    int lane = threadIdx.x & 31, warp = threadIdx.x >> 5;
    int row = blockIdx.x * 8 + warp;
    const float* drow = g_D + (size_t)row * NPTS;

    // Te = 20th largest of 32 precomputed 64-col chunk maxes (<= true 20th)
    float v = g_smax[(size_t)row * 32 + lane];
    #pragma unroll
    for (int k = 2; k <= 32; k <<= 1) {
        #pragma unroll
        for (int j = k >> 1; j > 0; j >>= 1) {
            float o = __shfl_xor_sync(FULL, v, j);
            bool takeMax = (((lane & k) == 0) == ((lane & j) == 0));
            v = takeMax ? fmaxf(v, o) : fminf(v, o);
        }
    }
    float Te = __shfl_sync(FULL, v, KNN - 1);

    // single-pass compact into smem
    unsigned lmask = (1u << lane) - 1u;
    unsigned cnt = 0;
    #pragma unroll 2
    for (int t = 0; t < NPTS / 128; t++) {
        int jb = t * 128 + lane * 4;
        float4 q = *(const float4*)&drow[jb];
        float vals[4] = {q.x, q.y, q.z, q.w};
        #pragma unroll
        for (int m = 0; m < 4; m++) {
            bool pass = vals[m] >= Te;
            unsigned mk = __ballot_sync(FULL, pass);
            if (pass) {
                unsigned pos = cnt + __popc(mk & lmask);
                if (pos < CAP) { sv[warp][pos] = vals[m]; si[warp][pos] = jb + m; }
            }
            cnt += __popc(mk);
        }
    }
    __syncwarp();
    if (lane == 0) g_cnt[row] = (int)cnt;

    if (cnt <= CAP) {
        float lv[8]; int li[8];
        #pragma unroll
        for (int q = 0; q < 8; q++) {
            int p = q * 32 + lane;
            bool in = p < (int)cnt;
            lv[q] = in ? sv[warp][p] : -FLT_MAX;
            li[q] = in ? si[warp][p] : 0x7FFFFFFF;
        }
        #pragma unroll 1
        for (int k = 0; k < KNN; k++) {
            float bv = -FLT_MAX; int bi = 0x7FFFFFFF, bq = 0;
            #pragma unroll
            for (int q = 0; q < 8; q++) {
                if (lv[q] > bv || (lv[q] == bv && li[q] < bi)) {
                    bv = lv[q]; bi = li[q]; bq = q;
                }
            }
            float wv = bv; int wi = bi;
            #pragma unroll
            for (int s = 16; s > 0; s >>= 1) {
                float ov = __shfl_xor_sync(FULL, wv, s);
                int   oi = __shfl_xor_sync(FULL, wi, s);
                if (ov > wv || (ov == wv && oi < wi)) { wv = ov; wi = oi; }
            }
            if (lane == 0) g_knn[(size_t)row * KNN + k] = wi;
            if (bv == wv && bi == wi) { lv[bq] = -FLT_MAX; li[bq] = 0x7FFFFFFF; }
        }
    }
    // cnt > CAP: g_knn left for k_topk_fb
}

// ---------------- top-K fallback: exact full-row path (rarely runs) --------
__global__ void k_topk_fb() {
    const unsigned FULL = 0xffffffffu;
    int lane = threadIdx.x & 31, warp = threadIdx.x >> 5;
    int row = blockIdx.x * 8 + warp;
    if (g_cnt[row] <= CAP) return;      // warp-uniform: whole warp exits

    const float* drow = g_D + (size_t)row * NPTS;
    float arr[KNN]; int ai[KNN];
    #pragma unroll
    for (int q = 0; q < KNN; q++) { arr[q] = -FLT_MAX; ai[q] = 0x7FFFFFFF; }
    #pragma unroll 1
    for (int t = 0; t < NPTS / 128; t++) {
        int jb = t * 128 + lane * 4;
        float4 v4 = *(const float4*)&drow[jb];
        float vv[4] = {v4.x, v4.y, v4.z, v4.w};
        #pragma unroll
        for (int m = 0; m < 4; m++) {
            float vx = vv[m];
            if (vx > arr[0]) {
                arr[0] = vx; ai[0] = jb + m;
                #pragma unroll
                for (int q = 0; q < KNN - 1; q++) {
                    if (arr[q + 1] < arr[q]) {
                        float tv = arr[q]; arr[q] = arr[q + 1]; arr[q + 1] = tv;
                        int ti = ai[q]; ai[q] = ai[q + 1]; ai[q + 1] = ti;
                    }
                }
            }
        }
    }
    #pragma unroll 1
    for (int k = 0; k < KNN; k++) {
        float cvv = arr[KNN - 1]; int cii = ai[KNN - 1];
        float wv = cvv; int wi = cii;
        #pragma unroll
        for (int s = 16; s > 0; s >>= 1) {
            float ov = __shfl_xor_sync(FULL, wv, s);
            int   oi = __shfl_xor_sync(FULL, wi, s);
            if (ov > wv || (ov == wv && oi < wi)) { wv = ov; wi = oi; }
        }
        if (lane == 0) g_knn[(size_t)row * KNN + k] = wi;
        if (cii == wi) {
            #pragma unroll
            for (int q = KNN - 1; q > 0; q--) { arr[q] = arr[q - 1]; ai[q] = ai[q - 1]; }
            arr[0] = -FLT_MAX; ai[0] = 0x7FFFFFFF;
        }
    }
}

// ---------------- Y = W2 X, Z = (W1-W2) X (fp32) ---------------------------
__global__ void k_yz(const float* __restrict__ feat, const float* __restrict__ W,
                     int C, int Cout, int bstr) {
    __shared__ float As[16][64];
    __shared__ float B1[16][64];
    __shared__ float B2[16][64];
    int b = blockIdx.z;
    int n0 = blockIdx.x * 64, o0 = blockIdx.y * 64;
    const float* fb = feat + (size_t)b * bstr;
    int tx = threadIdx.x & 15, ty = threadIdx.x >> 4;
    float aU[4][4] = {}, aY[4][4] = {};
    for (int c0 = 0; c0 < C; c0 += 16) {
        for (int e = threadIdx.x; e < 1024; e += 256) {
            int kk = e >> 6, nn = e & 63;
            int c = c0 + kk;
            As[kk][nn] = (c < C) ? fb[(size_t)c * NPTS + n0 + nn] : 0.f;
        }
        for (int e = threadIdx.x; e < 1024; e += 256) {
            int kk = e & 15, oo = e >> 4;
            int c = c0 + kk;
            float w1 = 0.f, w2 = 0.f;
            if (c < C) {
                const float* wr = W + (size_t)(o0 + oo) * (2 * C);
                w1 = wr[c]; w2 = wr[C + c];
            }
            B1[kk][oo] = w1; B2[kk][oo] = w2;
        }
        __syncthreads();
        #pragma unroll
        for (int kk = 0; kk < 16; kk++) {
            float4 a4 = *(const float4*)&As[kk][ty * 4];
            float4 b14 = *(const float4*)&B1[kk][tx * 4];
            float4 b24 = *(const float4*)&B2[kk][tx * 4];
            float av[4] = {a4.x, a4.y, a4.z, a4.w};
            float b1v[4] = {b14.x, b14.y, b14.z, b14.w};
            float b2v[4] = {b24.x, b24.y, b24.z, b24.w};
            #pragma unroll
            for (int r = 0; r < 4; r++)
                #pragma unroll
                for (int s = 0; s < 4; s++) {
                    aU[r][s] = fmaf(av[r], b1v[s], aU[r][s]);
                    aY[r][s] = fmaf(av[r], b2v[s], aY[r][s]);
                }
        }
        __syncthreads();
    }
    #pragma unroll
    for (int r = 0; r < 4; r++) {
        int n = n0 + ty * 4 + r;
        size_t base = ((size_t)b * NPTS + n) * 256 + o0 + tx * 4;
        float4 y, z;
        y.x = aY[r][0]; y.y = aY[r][1]; y.z = aY[r][2]; y.w = aY[r][3];
        z.x = aU[r][0] - y.x; z.y = aU[r][1] - y.y;
        z.z = aU[r][2] - y.z; z.w = aU[r][3] - y.w;
        *(float4*)&g_Y[base] = y;
        *(float4*)&g_Z[base] = z;
    }
}

// ---------------- gather-max + BN + lrelu -> xcat + bf16 mirrors -----------
__global__ void k_gather(float* __restrict__ out, const float* __restrict__ gam,
                         const float* __restrict__ bet, int Cout, int co) {
    __shared__ int   sidx[32 * KNN];
    __shared__ float sout[256 * 33];
    int b = blockIdx.y, n0 = blockIdx.x * 32;
    for (int e = threadIdx.x; e < 32 * KNN; e += blockDim.x)
        sidx[e] = g_knn[((size_t)b * NPTS + n0) * KNN + e];
    __syncthreads();
    int o = threadIdx.x;
    float sc = gam[o] * BN_RSQ, bi = bet[o];
    const float* Yb = g_Y + (size_t)b * NPTS * 256;
    const float* Zb = g_Z + (size_t)b * NPTS * 256;
    for (int nn = 0; nn < 32; nn++) {
        float m = -FLT_MAX;
        #pragma unroll
        for (int k = 0; k < KNN; k++) {
            int j = sidx[nn * KNN + k];
            m = fmaxf(m, Yb[(size_t)j * 256 + o]);
        }
        float v = Zb[(size_t)(n0 + nn) * 256 + o] + m;
        v = lrelu(fmaf(v, sc, bi));
        sout[o * 33 + nn] = v;
    }
    __syncthreads();
    float* ob = out + (size_t)b * CAT_BSTR;
    for (int e = threadIdx.x; e < Cout * 32; e += blockDim.x) {
        int oo = e >> 5, nn = e & 31;
        float v = sout[oo * 33 + nn];
        ob[(size_t)oo * NPTS + n0 + nn] = v;
        uint16_t h, l;
        split_bf16(v, h, l);
        size_t bidx = ((size_t)b * 512 + co + oo) * NPTS + n0 + nn;
        g_ch[bidx] = h;
        g_cl[bidx] = l;
    }
}

// ---------------- final pool from conv5 partials -> g_f --------------------
__global__ void k_pool2() {
    int b = blockIdx.y;
    int o = blockIdx.x * 256 + threadIdx.x;
    float m = -FLT_MAX, s = 0.f;
    #pragma unroll
    for (int nt = 0; nt < 16; nt++) {
        size_t base = (size_t)(b * 16 + nt) * 1024 + o;
        m = fmaxf(m, g_pmax[base]);
        s += g_psum[base];
    }
    g_f[b * 2048 + o] = m;
    g_f[b * 2048 + 1024 + o] = s * (1.0f / NPTS);
}

// ---------------- fc1: 2048->512, BN + lrelu -------------------------------
__global__ void k_fc1(const float* __restrict__ fw, const float* __restrict__ fb,
                      const float* __restrict__ gam, const float* __restrict__ bet) {
    int b = blockIdx.y;
    int w = threadIdx.x >> 5, lane = threadIdx.x & 31;
    int o = blockIdx.x * 8 + w;
    const float* f = g_f + b * 2048;
    const float* wr = fw + (size_t)o * 2048;
    float acc = 0.f;
    for (int c = lane; c < 2048; c += 32) acc = fmaf(f[c], wr[c], acc);
    #pragma unroll
    for (int s = 16; s > 0; s >>= 1) acc += __shfl_xor_sync(0xffffffffu, acc, s);
    if (lane == 0) {
        float v = acc + fb[o];
        v = lrelu(fmaf(v, gam[o] * BN_RSQ, bet[o]));
        g_fc1[b * 512 + o] = v;
    }
}

// ---------------- fc2: 512->256, BN (no lrelu) -> d_out --------------------
__global__ void k_fc2(const float* __restrict__ fw, const float* __restrict__ fb,
                      const float* __restrict__ gam, const float* __restrict__ bet,
                      float* __restrict__ out) {
    int b = blockIdx.y;
    int w = threadIdx.x >> 5, lane = threadIdx.x & 31;
    int o = blockIdx.x * 8 + w;
    const float* f = g_fc1 + b * 512;
    const float* wr = fw + (size_t)o * 512;
    float acc = 0.f;
    for (int c = lane; c < 512; c += 32) acc = fmaf(f[c], wr[c], acc);
    #pragma unroll
    for (int s = 16; s > 0; s >>= 1) acc += __shfl_xor_sync(0xffffffffu, acc, s);
    if (lane == 0) {
        float v = acc + fb[o];
        out[b * 256 + o] = fmaf(v, gam[o] * BN_RSQ, bet[o]);
    }
}

// ---------------- driver ---------------------------------------------------
static void run_edge(const float* feat, int C, int bstr,
                     const uint16_t* dh, const uint16_t* dl, int Ceff, int bfstr,
                     const float* W, const float* gam, const float* bet,
                     float* out, int Cout, int co) {
    k_xx<<<(BATCH * NPTS + 255) / 256, 256>>>(feat, C, bstr);
    k_dist_mma<<<dim3(NPTS / 128, NPTS / 128, BATCH), 256>>>(dh, dl, Ceff, bfstr);
    k_topk<<<BATCH * NPTS / 8, 256>>>();
    k_topk_fb<<<BATCH * NPTS / 8, 256>>>();
    k_yz<<<dim3(NPTS / 64, Cout / 64, BATCH), 256>>>(feat, W, C, Cout, bstr);
    k_gather<<<dim3(NPTS / 32, BATCH), Cout>>>(out, gam, bet, Cout, co);
}

extern "C" void kernel_launch(void* const* d_in, const int* in_sizes, int n_in,
                              void* d_out, int out_size) {
    const float* pts = (const float*)d_in[0];
    const float* w1 = (const float*)d_in[1];
    const float* g1 = (const float*)d_in[2];
    const float* b1 = (const float*)d_in[3];
    const float* w2 = (const float*)d_in[4];
    const float* g2 = (const float*)d_in[5];
    const float* b2 = (const float*)d_in[6];
    const float* w3 = (const float*)d_in[7];
    const float* g3 = (const float*)d_in[8];
    const float* b3 = (const float*)d_in[9];
    const float* w4 = (const float*)d_in[10];
    const float* g4 = (const float*)d_in[11];
    const float* b4 = (const float*)d_in[12];
    const float* w5 = (const float*)d_in[13];
    const float* g5 = (const float*)d_in[14];
    const float* b5 = (const float*)d_in[15];
    const float* fw1 = (const float*)d_in[16];
    const float* fb1 = (const float*)d_in[17];
    const float* g6 = (const float*)d_in[18];
    const float* b6 = (const float*)d_in[19];
    const float* fw2 = (const float*)d_in[20];
    const float* fb2 = (const float*)d_in[21];
    const float* g7 = (const float*)d_in[22];
    const float* b7 = (const float*)d_in[23];

    float *x0, *xcat;
    uint16_t *x0h, *x0l, *ch, *cl;
    cudaGetSymbolAddress((void**)&x0, g_x0);
    cudaGetSymbolAddress((void**)&xcat, g_xcat);
    cudaGetSymbolAddress((void**)&x0h, g_x0h);
    cudaGetSymbolAddress((void**)&x0l, g_x0l);
    cudaGetSymbolAddress((void**)&ch, g_ch);
    cudaGetSymbolAddress((void**)&cl, g_cl);
    float* x1 = xcat;                  // ch 0..63
    float* x2 = xcat + 64 * NPTS;      // ch 64..127
    float* x3 = xcat + 128 * NPTS;     // ch 128..255
    float* x4 = xcat + 256 * NPTS;     // ch 256..511

    k_transpose<<<(BATCH * NPTS + 255) / 256, 256>>>(pts);
    run_edge(x0, 3,   3 * NPTS, x0h, x0l, 16, 16 * NPTS,
             w1, g1, b1, x1, 64, 0);
    run_edge(x1, 64,  CAT_BSTR, ch,              cl,              64,  CAT_BSTR,
             w2, g2, b2, x2, 64, 64);
    run_edge(x2, 64,  CAT_BSTR, ch + 64 * NPTS,  cl + 64 * NPTS,  64,  CAT_BSTR,
             w3, g3, b3, x3, 128, 128);
    run_edge(x3, 128, CAT_BSTR, ch + 128 * NPTS, cl + 128 * NPTS, 128, CAT_BSTR,
             w4, g4, b4, x4, 256, 256);
    k_cvt_w5<<<(1024 * 512 + 255) / 256, 256>>>(w5);
    k_conv5_mma<<<dim3(NPTS / 128, 1024 / 128, BATCH), 256>>>(g5, b5);
    k_pool2<<<dim3(1024 / 256, BATCH), 256>>>();
    k_fc1<<<dim3(512 / 8, BATCH), 256>>>(fw1, fb1, g6, b6);
    k_fc2<<<dim3(256 / 8, BATCH), 256>>>(fw2, fb2, g7, b7, (float*)d_out);
}